// round 4
// baseline (speedup 1.0000x reference)
#include <cuda_runtime.h>
#include <math.h>

#define BB 4
#define NN 2048
#define DD 512
#define HH 8
#define DKK 64

// Scratch: __device__ globals (no allocation allowed in kernel_launch).
__device__ float g_Qp[BB * NN * DD];        // 16 MB
__device__ float g_Kp[BB * NN * DD];        // 16 MB
__device__ float g_Vp[BB * NN * DD];        // 16 MB
__device__ float g_Zinv[(size_t)BB * NN * NN];  // 64 MB
__device__ float g_A[BB * NN * DD];         // 16 MB

// ---------------------------------------------------------------------------
// Kernel 1: project Q, K, V with the SAME Wq/bq (faithful to source bug).
//   Y[row,e] = sum_d X[row,d] * W[e,d] + bias[e]
// Tiles: 64x64, BK=16, 256 threads, 4x4 per thread.
// ---------------------------------------------------------------------------
__global__ void proj_kernel(const float* __restrict__ Q,
                            const float* __restrict__ K,
                            const float* __restrict__ V,
                            const float* __restrict__ W,
                            const float* __restrict__ bias) {
    const float* X = (blockIdx.z == 0) ? Q : (blockIdx.z == 1) ? K : V;
    float* Y = (blockIdx.z == 0) ? g_Qp : (blockIdx.z == 1) ? g_Kp : g_Vp;

    __shared__ float sX[16][65];  // [k][row]
    __shared__ float sW[16][65];  // [k][e]

    const int tx = threadIdx.x & 15;
    const int ty = threadIdx.x >> 4;
    const int row0 = blockIdx.y * 64;
    const int e0 = blockIdx.x * 64;

    float acc[4][4] = {};

    for (int k0 = 0; k0 < DD; k0 += 16) {
        for (int i = threadIdx.x; i < 64 * 16; i += 256) {
            int r = i >> 4, kk = i & 15;
            sX[kk][r] = X[(size_t)(row0 + r) * DD + k0 + kk];
            sW[kk][r] = W[(size_t)(e0 + r) * DD + k0 + kk];
        }
        __syncthreads();
        #pragma unroll
        for (int kk = 0; kk < 16; kk++) {
            float a[4], b[4];
            #pragma unroll
            for (int i = 0; i < 4; i++) a[i] = sX[kk][ty * 4 + i];
            #pragma unroll
            for (int j = 0; j < 4; j++) b[j] = sW[kk][tx * 4 + j];
            #pragma unroll
            for (int i = 0; i < 4; i++)
                #pragma unroll
                for (int j = 0; j < 4; j++) acc[i][j] += a[i] * b[j];
        }
        __syncthreads();
    }

    #pragma unroll
    for (int i = 0; i < 4; i++) {
        #pragma unroll
        for (int j = 0; j < 4; j++) {
            int e = e0 + tx * 4 + j;
            Y[(size_t)(row0 + ty * 4 + i) * DD + e] = acc[i][j] + bias[e];
        }
    }
}

// ---------------------------------------------------------------------------
// Kernel 2: Zinv[b,n,m] = 1 / sum_h exp( (q_h(n) . k_h(m)) / 8 )
// Softmax over HEADS axis -> per (n,m) the 8 head-scores are 8 disjoint
// 64-dim chunks of the full 512-dim dot product.
// ---------------------------------------------------------------------------
__global__ void zinv_kernel() {
    const int b = blockIdx.z;
    const int n0 = blockIdx.y * 64;
    const int m0 = blockIdx.x * 64;
    const float* Qp = g_Qp + (size_t)b * NN * DD;
    const float* Kp = g_Kp + (size_t)b * NN * DD;

    __shared__ float sQ[16][65];  // [k][n]
    __shared__ float sK[16][65];  // [k][m]

    const int tx = threadIdx.x & 15;
    const int ty = threadIdx.x >> 4;

    float z[4][4] = {};

    for (int h = 0; h < HH; h++) {
        float dot[4][4] = {};
        for (int k0 = 0; k0 < DKK; k0 += 16) {
            const int kb = h * DKK + k0;
            for (int i = threadIdx.x; i < 64 * 16; i += 256) {
                int r = i >> 4, kk = i & 15;
                sQ[kk][r] = Qp[(size_t)(n0 + r) * DD + kb + kk];
                sK[kk][r] = Kp[(size_t)(m0 + r) * DD + kb + kk];
            }
            __syncthreads();
            #pragma unroll
            for (int kk = 0; kk < 16; kk++) {
                float a[4], bb[4];
                #pragma unroll
                for (int i = 0; i < 4; i++) a[i] = sQ[kk][ty * 4 + i];
                #pragma unroll
                for (int j = 0; j < 4; j++) bb[j] = sK[kk][tx * 4 + j];
                #pragma unroll
                for (int i = 0; i < 4; i++)
                    #pragma unroll
                    for (int j = 0; j < 4; j++) dot[i][j] += a[i] * bb[j];
            }
            __syncthreads();
        }
        #pragma unroll
        for (int i = 0; i < 4; i++)
            #pragma unroll
            for (int j = 0; j < 4; j++) z[i][j] += __expf(dot[i][j] * 0.125f);
    }

    #pragma unroll
    for (int i = 0; i < 4; i++)
        #pragma unroll
        for (int j = 0; j < 4; j++)
            g_Zinv[((size_t)b * NN + n0 + ty * 4 + i) * NN + m0 + tx * 4 + j] =
                1.0f / z[i][j];
}

// ---------------------------------------------------------------------------
// Kernel 3: per-head attention with precomputed Zinv (no streaming softmax).
//   A[b,n,h*64+d] = sum_m exp(S_h(n,m)/8) * Zinv[b,n,m] * Vp[b,m,h*64+d]
// Block: one (b,h,n-tile of 64). m-chunks of 32.
// ---------------------------------------------------------------------------
__global__ void attn_kernel() {
    const int b = blockIdx.z;
    const int h = blockIdx.y;
    const int n0 = blockIdx.x * 64;

    const float* Qp = g_Qp + (size_t)b * NN * DD + h * DKK;
    const float* Kp = g_Kp + (size_t)b * NN * DD + h * DKK;
    const float* Vp = g_Vp + (size_t)b * NN * DD + h * DKK;
    const float* Zb = g_Zinv + (size_t)b * NN * NN;

    __shared__ float sQ[64][65];  // [n][d]
    __shared__ float sK[32][65];  // [m][d]
    __shared__ float sV[32][64];  // [m][d]
    __shared__ float sP[64][33];  // [n][m]

    const int tx = threadIdx.x & 15;
    const int ty = threadIdx.x >> 4;

    // Load Q tile once (head slice, 64x64)
    for (int i = threadIdx.x; i < 64 * 64; i += 256) {
        int r = i >> 6, d = i & 63;
        sQ[r][d] = Qp[(size_t)(n0 + r) * DD + d];
    }

    float acc[4][4] = {};

    for (int m0 = 0; m0 < NN; m0 += 32) {
        for (int i = threadIdx.x; i < 32 * 64; i += 256) {
            int r = i >> 6, d = i & 63;
            sK[r][d] = Kp[(size_t)(m0 + r) * DD + d];
            sV[r][d] = Vp[(size_t)(m0 + r) * DD + d];
        }
        __syncthreads();

        // S phase: 64n x 32m, each thread 4n x 2m
        float s[4][2] = {};
        #pragma unroll 8
        for (int d = 0; d < 64; d++) {
            float a[4], bb[2];
            #pragma unroll
            for (int i = 0; i < 4; i++) a[i] = sQ[ty * 4 + i][d];
            #pragma unroll
            for (int j = 0; j < 2; j++) bb[j] = sK[tx * 2 + j][d];
            #pragma unroll
            for (int i = 0; i < 4; i++)
                #pragma unroll
                for (int j = 0; j < 2; j++) s[i][j] += a[i] * bb[j];
        }
        #pragma unroll
        for (int i = 0; i < 4; i++) {
            #pragma unroll
            for (int j = 0; j < 2; j++) {
                int nn = n0 + ty * 4 + i;
                int mm = m0 + tx * 2 + j;
                sP[ty * 4 + i][tx * 2 + j] =
                    __expf(s[i][j] * 0.125f) * Zb[(size_t)nn * NN + mm];
            }
        }
        __syncthreads();

        // PV phase: acc[n][d] += P[n][m] * V[m][d]
        #pragma unroll 8
        for (int mm = 0; mm < 32; mm++) {
            float a[4], bb[4];
            #pragma unroll
            for (int i = 0; i < 4; i++) a[i] = sP[ty * 4 + i][mm];
            #pragma unroll
            for (int j = 0; j < 4; j++) bb[j] = sV[mm][tx * 4 + j];
            #pragma unroll
            for (int i = 0; i < 4; i++)
                #pragma unroll
                for (int j = 0; j < 4; j++) acc[i][j] += a[i] * bb[j];
        }
        __syncthreads();
    }

    #pragma unroll
    for (int i = 0; i < 4; i++)
        #pragma unroll
        for (int j = 0; j < 4; j++)
            g_A[((size_t)b * NN + n0 + ty * 4 + i) * DD + h * DKK + tx * 4 + j] =
                acc[i][j];
}

// ---------------------------------------------------------------------------
// Kernel 4: output projection. out[row,e] = sum_d A[row,d]*Wo[e,d] + bo[e]
// ---------------------------------------------------------------------------
__global__ void outproj_kernel(const float* __restrict__ Wo,
                               const float* __restrict__ bo,
                               float* __restrict__ out) {
    __shared__ float sX[16][65];
    __shared__ float sW[16][65];

    const int tx = threadIdx.x & 15;
    const int ty = threadIdx.x >> 4;
    const int row0 = blockIdx.y * 64;
    const int e0 = blockIdx.x * 64;

    float acc[4][4] = {};

    for (int k0 = 0; k0 < DD; k0 += 16) {
        for (int i = threadIdx.x; i < 64 * 16; i += 256) {
            int r = i >> 4, kk = i & 15;
            sX[kk][r] = g_A[(size_t)(row0 + r) * DD + k0 + kk];
            sW[kk][r] = Wo[(size_t)(e0 + r) * DD + k0 + kk];
        }
        __syncthreads();
        #pragma unroll
        for (int kk = 0; kk < 16; kk++) {
            float a[4], b[4];
            #pragma unroll
            for (int i = 0; i < 4; i++) a[i] = sX[kk][ty * 4 + i];
            #pragma unroll
            for (int j = 0; j < 4; j++) b[j] = sW[kk][tx * 4 + j];
            #pragma unroll
            for (int i = 0; i < 4; i++)
                #pragma unroll
                for (int j = 0; j < 4; j++) acc[i][j] += a[i] * b[j];
        }
        __syncthreads();
    }

    #pragma unroll
    for (int i = 0; i < 4; i++) {
        #pragma unroll
        for (int j = 0; j < 4; j++) {
            int e = e0 + tx * 4 + j;
            out[(size_t)(row0 + ty * 4 + i) * DD + e] = acc[i][j] + bo[e];
        }
    }
}

extern "C" void kernel_launch(void* const* d_in, const int* in_sizes, int n_in,
                              void* d_out, int out_size) {
    const float* Q  = (const float*)d_in[0];
    const float* K  = (const float*)d_in[1];
    const float* V  = (const float*)d_in[2];
    const float* Wq = (const float*)d_in[3];
    const float* bq = (const float*)d_in[4];
    const float* Wo = (const float*)d_in[5];
    const float* bo = (const float*)d_in[6];
    float* out = (float*)d_out;

    proj_kernel<<<dim3(DD / 64, (BB * NN) / 64, 3), 256>>>(Q, K, V, Wq, bq);
    zinv_kernel<<<dim3(NN / 64, NN / 64, BB), 256>>>();
    attn_kernel<<<dim3(NN / 64, HH, BB), 256>>>();
    outproj_kernel<<<dim3(DD / 64, (BB * NN) / 64, 1), 256>>>(Wo, bo, out);
}

// round 5
// speedup vs baseline: 2.3814x; 2.3814x over previous
#include <cuda_runtime.h>
#include <math.h>
#include <stdint.h>

#define BB 4
#define NN 2048
#define DD 512
#define HH 8
#define DKK 64

// Scratch (__device__ globals; no allocation allowed anywhere).
__device__ float g_Qp[BB * NN * DD];            // 16 MB
__device__ float g_Kp[BB * NN * DD];            // 16 MB
__device__ float g_Vp[BB * NN * DD];            // 16 MB
__device__ float g_Zinv[(size_t)BB * NN * NN];  // 64 MB
__device__ float g_A[BB * NN * DD];             // 16 MB

__device__ __forceinline__ uint32_t f2tf(float x) {
    uint32_t r;
    asm("cvt.rna.tf32.f32 %0, %1;" : "=r"(r) : "f"(x));
    return r;
}

__device__ __forceinline__ void mma8(float c[4], const uint32_t a[4],
                                     const uint32_t b[2]) {
    asm volatile(
        "mma.sync.aligned.m16n8k8.row.col.f32.tf32.tf32.f32 "
        "{%0,%1,%2,%3},{%4,%5,%6,%7},{%8,%9},{%0,%1,%2,%3};"
        : "+f"(c[0]), "+f"(c[1]), "+f"(c[2]), "+f"(c[3])
        : "r"(a[0]), "r"(a[1]), "r"(a[2]), "r"(a[3]), "r"(b[0]), "r"(b[1]));
}

// ---------------------------------------------------------------------------
// Generic 512-K GEMM: Y[row,e] = sum_d X[row,d]*W[e,d] + bias[e]
// Tile 128x128, BK=16, 256 threads, 8 warps of 64x32.
// Used for all three input projections AND the output projection.
// ---------------------------------------------------------------------------
__global__ __launch_bounds__(256) void gemm512_kernel(
    const float* __restrict__ X, const float* __restrict__ W,
    const float* __restrict__ bias, float* __restrict__ Y) {
    __shared__ uint32_t sA[128][20];
    __shared__ uint32_t sB[128][20];

    const int tid = threadIdx.x;
    const int lane = tid & 31;
    const int warp = tid >> 5;
    const int wR = warp >> 2;  // 0..1
    const int wC = warp & 3;   // 0..3
    const int row0 = blockIdx.y * 128;
    const int e0 = blockIdx.x * 128;

    float acc[4][4][4] = {};

    for (int k0 = 0; k0 < DD; k0 += 16) {
        #pragma unroll
        for (int it = 0; it < 2; it++) {
            int i = tid + it * 256;
            int r = i >> 2, kv = (i & 3) * 4;
            float4 va = *(const float4*)&X[(size_t)(row0 + r) * DD + k0 + kv];
            sA[r][kv + 0] = f2tf(va.x);
            sA[r][kv + 1] = f2tf(va.y);
            sA[r][kv + 2] = f2tf(va.z);
            sA[r][kv + 3] = f2tf(va.w);
            float4 vb = *(const float4*)&W[(size_t)(e0 + r) * DD + k0 + kv];
            sB[r][kv + 0] = f2tf(vb.x);
            sB[r][kv + 1] = f2tf(vb.y);
            sB[r][kv + 2] = f2tf(vb.z);
            sB[r][kv + 3] = f2tf(vb.w);
        }
        __syncthreads();

        #pragma unroll
        for (int kk = 0; kk < 16; kk += 8) {
            uint32_t af[4][4], bf[4][2];
            #pragma unroll
            for (int mt = 0; mt < 4; mt++) {
                int r = wR * 64 + mt * 16 + (lane >> 2);
                af[mt][0] = sA[r][kk + (lane & 3)];
                af[mt][1] = sA[r + 8][kk + (lane & 3)];
                af[mt][2] = sA[r][kk + 4 + (lane & 3)];
                af[mt][3] = sA[r + 8][kk + 4 + (lane & 3)];
            }
            #pragma unroll
            for (int nt = 0; nt < 4; nt++) {
                int c = wC * 32 + nt * 8 + (lane >> 2);
                bf[nt][0] = sB[c][kk + (lane & 3)];
                bf[nt][1] = sB[c][kk + 4 + (lane & 3)];
            }
            #pragma unroll
            for (int mt = 0; mt < 4; mt++)
                #pragma unroll
                for (int nt = 0; nt < 4; nt++) mma8(acc[mt][nt], af[mt], bf[nt]);
        }
        __syncthreads();
    }

    #pragma unroll
    for (int mt = 0; mt < 4; mt++) {
        int r = row0 + wR * 64 + mt * 16 + (lane >> 2);
        #pragma unroll
        for (int nt = 0; nt < 4; nt++) {
            int c = e0 + wC * 32 + nt * 8 + (lane & 3) * 2;
            float b0 = bias[c], b1 = bias[c + 1];
            *(float2*)&Y[(size_t)r * DD + c] =
                make_float2(acc[mt][nt][0] + b0, acc[mt][nt][1] + b1);
            *(float2*)&Y[(size_t)(r + 8) * DD + c] =
                make_float2(acc[mt][nt][2] + b0, acc[mt][nt][3] + b1);
        }
    }
}

// ---------------------------------------------------------------------------
// Zinv[b,n,m] = 1 / sum_h exp( (q_h(n).k_h(m)) / 8 )
// Tile 128x128, 512 threads, 16 warps of 32x32. Heads separable (softmax is
// over the heads axis), so accumulate per-head 64-deep dots then exp-add.
// ---------------------------------------------------------------------------
__global__ __launch_bounds__(512) void zinv_kernel() {
    __shared__ uint32_t sQ[128][20];
    __shared__ uint32_t sK[128][20];

    const int tid = threadIdx.x;
    const int lane = tid & 31;
    const int warp = tid >> 5;
    const int wR = warp >> 2;  // 0..3
    const int wC = warp & 3;   // 0..3
    const int b = blockIdx.z;
    const int n0 = blockIdx.y * 128;
    const int m0 = blockIdx.x * 128;
    const float* Qp = g_Qp + (size_t)b * NN * DD;
    const float* Kp = g_Kp + (size_t)b * NN * DD;

    float z[2][4][4] = {};

    for (int h = 0; h < HH; h++) {
        float dot[2][4][4] = {};
        for (int k0 = 0; k0 < DKK; k0 += 16) {
            const int kb = h * DKK + k0;
            {
                int r = tid >> 2, kv = (tid & 3) * 4;
                float4 q = *(const float4*)&Qp[(size_t)(n0 + r) * DD + kb + kv];
                sQ[r][kv + 0] = f2tf(q.x);
                sQ[r][kv + 1] = f2tf(q.y);
                sQ[r][kv + 2] = f2tf(q.z);
                sQ[r][kv + 3] = f2tf(q.w);
                float4 k4 = *(const float4*)&Kp[(size_t)(m0 + r) * DD + kb + kv];
                sK[r][kv + 0] = f2tf(k4.x);
                sK[r][kv + 1] = f2tf(k4.y);
                sK[r][kv + 2] = f2tf(k4.z);
                sK[r][kv + 3] = f2tf(k4.w);
            }
            __syncthreads();

            #pragma unroll
            for (int kk = 0; kk < 16; kk += 8) {
                uint32_t af[2][4], bf[4][2];
                #pragma unroll
                for (int mt = 0; mt < 2; mt++) {
                    int r = wR * 32 + mt * 16 + (lane >> 2);
                    af[mt][0] = sQ[r][kk + (lane & 3)];
                    af[mt][1] = sQ[r + 8][kk + (lane & 3)];
                    af[mt][2] = sQ[r][kk + 4 + (lane & 3)];
                    af[mt][3] = sQ[r + 8][kk + 4 + (lane & 3)];
                }
                #pragma unroll
                for (int nt = 0; nt < 4; nt++) {
                    int c = wC * 32 + nt * 8 + (lane >> 2);
                    bf[nt][0] = sK[c][kk + (lane & 3)];
                    bf[nt][1] = sK[c][kk + 4 + (lane & 3)];
                }
                #pragma unroll
                for (int mt = 0; mt < 2; mt++)
                    #pragma unroll
                    for (int nt = 0; nt < 4; nt++) mma8(dot[mt][nt], af[mt], bf[nt]);
            }
            __syncthreads();
        }
        #pragma unroll
        for (int mt = 0; mt < 2; mt++)
            #pragma unroll
            for (int nt = 0; nt < 4; nt++)
                #pragma unroll
                for (int i = 0; i < 4; i++)
                    z[mt][nt][i] += __expf(dot[mt][nt][i] * 0.125f);
    }

    #pragma unroll
    for (int mt = 0; mt < 2; mt++) {
        int r = n0 + wR * 32 + mt * 16 + (lane >> 2);
        #pragma unroll
        for (int nt = 0; nt < 4; nt++) {
            int c = m0 + wC * 32 + nt * 8 + (lane & 3) * 2;
            *(float2*)&g_Zinv[((size_t)b * NN + r) * NN + c] =
                make_float2(1.0f / z[mt][nt][0], 1.0f / z[mt][nt][1]);
            *(float2*)&g_Zinv[((size_t)b * NN + r + 8) * NN + c] =
                make_float2(1.0f / z[mt][nt][2], 1.0f / z[mt][nt][3]);
        }
    }
}

// ---------------------------------------------------------------------------
// Attention with precomputed Zinv. Per block: one (b,h,n-tile of 64).
// m-chunks of 32. 128 threads, 4 warps arranged 2x2.
//  S phase: warp 32x16 of the 64x32 S tile (contract 64).
//  PV phase: warp 32x32 of the 64x64 O tile (contract 32 per chunk).
// ---------------------------------------------------------------------------
__global__ __launch_bounds__(128) void attn_kernel() {
    __shared__ uint32_t sQ[64][68];
    __shared__ uint32_t sK[32][68];
    __shared__ uint32_t sP[64][36];
    __shared__ uint32_t sVt[64][36];

    const int tid = threadIdx.x;
    const int lane = tid & 31;
    const int warp = tid >> 5;
    const int wR = warp >> 1;  // 0..1
    const int wC = warp & 1;   // 0..1
    const int b = blockIdx.z;
    const int h = blockIdx.y;
    const int n0 = blockIdx.x * 64;

    const float* Qp = g_Qp + (size_t)b * NN * DD + h * DKK;
    const float* Kp = g_Kp + (size_t)b * NN * DD + h * DKK;
    const float* Vp = g_Vp + (size_t)b * NN * DD + h * DKK;
    const float* Zb = g_Zinv + (size_t)b * NN * NN;

    // Load Q tile (64 x 64) once, tf32-converted.
    for (int i = tid; i < 64 * 16; i += 128) {
        int r = i >> 4, kv = (i & 15) * 4;
        float4 q = *(const float4*)&Qp[(size_t)(n0 + r) * DD + kv];
        sQ[r][kv + 0] = f2tf(q.x);
        sQ[r][kv + 1] = f2tf(q.y);
        sQ[r][kv + 2] = f2tf(q.z);
        sQ[r][kv + 3] = f2tf(q.w);
    }

    float accO[2][4][4] = {};

    for (int m0 = 0; m0 < NN; m0 += 32) {
        // K tile 32x64 (row-major in smem)
        for (int i = tid; i < 32 * 16; i += 128) {
            int r = i >> 4, kv = (i & 15) * 4;
            float4 k4 = *(const float4*)&Kp[(size_t)(m0 + r) * DD + kv];
            sK[r][kv + 0] = f2tf(k4.x);
            sK[r][kv + 1] = f2tf(k4.y);
            sK[r][kv + 2] = f2tf(k4.z);
            sK[r][kv + 3] = f2tf(k4.w);
        }
        // V tile transposed: sVt[d][m] = V[m0+m][d].
        // Lane mapping m = i&31 keeps STS conflict-free (all lanes same row).
        for (int i = tid; i < 32 * 16; i += 128) {
            int m = i & 31, dv = (i >> 5) * 4;
            float4 v4 = *(const float4*)&Vp[(size_t)(m0 + m) * DD + dv];
            sVt[dv + 0][m] = f2tf(v4.x);
            sVt[dv + 1][m] = f2tf(v4.y);
            sVt[dv + 2][m] = f2tf(v4.z);
            sVt[dv + 3][m] = f2tf(v4.w);
        }
        __syncthreads();

        // ---- S phase: S = Q.K^T (64x32, contract 64) ----
        float accS[2][2][4] = {};
        #pragma unroll
        for (int kk = 0; kk < 64; kk += 8) {
            uint32_t af[2][4], bf[2][2];
            #pragma unroll
            for (int mt = 0; mt < 2; mt++) {
                int r = wR * 32 + mt * 16 + (lane >> 2);
                af[mt][0] = sQ[r][kk + (lane & 3)];
                af[mt][1] = sQ[r + 8][kk + (lane & 3)];
                af[mt][2] = sQ[r][kk + 4 + (lane & 3)];
                af[mt][3] = sQ[r + 8][kk + 4 + (lane & 3)];
            }
            #pragma unroll
            for (int nt = 0; nt < 2; nt++) {
                int c = wC * 16 + nt * 8 + (lane >> 2);
                bf[nt][0] = sK[c][kk + (lane & 3)];
                bf[nt][1] = sK[c][kk + 4 + (lane & 3)];
            }
            #pragma unroll
            for (int mt = 0; mt < 2; mt++)
                #pragma unroll
                for (int nt = 0; nt < 2; nt++) mma8(accS[mt][nt], af[mt], bf[nt]);
        }

        // P = exp(S/8) * Zinv  ->  sP (tf32)
        #pragma unroll
        for (int mt = 0; mt < 2; mt++) {
            int rl = wR * 32 + mt * 16 + (lane >> 2);
            #pragma unroll
            for (int nt = 0; nt < 2; nt++) {
                int cl = wC * 16 + nt * 8 + (lane & 3) * 2;
                float2 z0 = *(const float2*)&Zb[(size_t)(n0 + rl) * NN + m0 + cl];
                float2 z1 =
                    *(const float2*)&Zb[(size_t)(n0 + rl + 8) * NN + m0 + cl];
                sP[rl][cl] = f2tf(__expf(accS[mt][nt][0] * 0.125f) * z0.x);
                sP[rl][cl + 1] = f2tf(__expf(accS[mt][nt][1] * 0.125f) * z0.y);
                sP[rl + 8][cl] = f2tf(__expf(accS[mt][nt][2] * 0.125f) * z1.x);
                sP[rl + 8][cl + 1] = f2tf(__expf(accS[mt][nt][3] * 0.125f) * z1.y);
            }
        }
        __syncthreads();

        // ---- PV phase: O += P.V (64x64, contract 32) ----
        #pragma unroll
        for (int kk = 0; kk < 32; kk += 8) {
            uint32_t af[2][4], bf[4][2];
            #pragma unroll
            for (int mt = 0; mt < 2; mt++) {
                int r = wR * 32 + mt * 16 + (lane >> 2);
                af[mt][0] = sP[r][kk + (lane & 3)];
                af[mt][1] = sP[r + 8][kk + (lane & 3)];
                af[mt][2] = sP[r][kk + 4 + (lane & 3)];
                af[mt][3] = sP[r + 8][kk + 4 + (lane & 3)];
            }
            #pragma unroll
            for (int nt = 0; nt < 4; nt++) {
                int c = wC * 32 + nt * 8 + (lane >> 2);
                bf[nt][0] = sVt[c][kk + (lane & 3)];
                bf[nt][1] = sVt[c][kk + 4 + (lane & 3)];
            }
            #pragma unroll
            for (int mt = 0; mt < 2; mt++)
                #pragma unroll
                for (int nt = 0; nt < 4; nt++) mma8(accO[mt][nt], af[mt], bf[nt]);
        }
        __syncthreads();
    }

    #pragma unroll
    for (int mt = 0; mt < 2; mt++) {
        int r = n0 + wR * 32 + mt * 16 + (lane >> 2);
        #pragma unroll
        for (int nt = 0; nt < 4; nt++) {
            int c = h * DKK + wC * 32 + nt * 8 + (lane & 3) * 2;
            *(float2*)&g_A[((size_t)b * NN + r) * DD + c] =
                make_float2(accO[mt][nt][0], accO[mt][nt][1]);
            *(float2*)&g_A[((size_t)b * NN + r + 8) * DD + c] =
                make_float2(accO[mt][nt][2], accO[mt][nt][3]);
        }
    }
}

extern "C" void kernel_launch(void* const* d_in, const int* in_sizes, int n_in,
                              void* d_out, int out_size) {
    const float* Q = (const float*)d_in[0];
    const float* K = (const float*)d_in[1];
    const float* V = (const float*)d_in[2];
    const float* Wq = (const float*)d_in[3];
    const float* bq = (const float*)d_in[4];
    const float* Wo = (const float*)d_in[5];
    const float* bo = (const float*)d_in[6];
    float* out = (float*)d_out;

    void *pQp = nullptr, *pKp = nullptr, *pVp = nullptr, *pA = nullptr;
    cudaGetSymbolAddress(&pQp, g_Qp);
    cudaGetSymbolAddress(&pKp, g_Kp);
    cudaGetSymbolAddress(&pVp, g_Vp);
    cudaGetSymbolAddress(&pA, g_A);

    dim3 gGemm(DD / 128, (BB * NN) / 128);  // (4, 64)
    gemm512_kernel<<<gGemm, 256>>>(Q, Wq, bq, (float*)pQp);
    gemm512_kernel<<<gGemm, 256>>>(K, Wq, bq, (float*)pKp);
    gemm512_kernel<<<gGemm, 256>>>(V, Wq, bq, (float*)pVp);
    zinv_kernel<<<dim3(NN / 128, NN / 128, BB), 512>>>();
    attn_kernel<<<dim3(NN / 64, HH, BB), 128>>>();
    gemm512_kernel<<<gGemm, 256>>>((const float*)pA, Wo, bo, out);
}

// round 6
// speedup vs baseline: 3.0590x; 1.2845x over previous
#include <cuda_runtime.h>
#include <math.h>
#include <stdint.h>

#define BB 4
#define NN 2048
#define DD 512
#define HH 8
#define DKK 64

// Scratch (__device__ globals; no allocation allowed anywhere).
__device__ float g_Qp[BB * NN * DD];            // 16 MB
__device__ float g_Kp[BB * NN * DD];            // 16 MB
__device__ float g_Vp[BB * NN * DD];            // 16 MB
__device__ float g_Zinv[(size_t)BB * NN * NN];  // 64 MB
__device__ float g_A[BB * NN * DD];             // 16 MB

__device__ __forceinline__ uint32_t f2tf(float x) {
    uint32_t r;
    asm("cvt.rna.tf32.f32 %0, %1;" : "=r"(r) : "f"(x));
    return r;
}

__device__ __forceinline__ uint4 f4totf(float4 v) {
    return make_uint4(f2tf(v.x), f2tf(v.y), f2tf(v.z), f2tf(v.w));
}

__device__ __forceinline__ void mma8(float c[4], const uint32_t a[4],
                                     const uint32_t b[2]) {
    asm volatile(
        "mma.sync.aligned.m16n8k8.row.col.f32.tf32.tf32.f32 "
        "{%0,%1,%2,%3},{%4,%5,%6,%7},{%8,%9},{%0,%1,%2,%3};"
        : "+f"(c[0]), "+f"(c[1]), "+f"(c[2]), "+f"(c[3])
        : "r"(a[0]), "r"(a[1]), "r"(a[2]), "r"(a[3]), "r"(b[0]), "r"(b[1]));
}

// ---------------------------------------------------------------------------
// Generic 512-K GEMM: Y[row,e] = sum_d X[row,d]*W[e,d] + bias[e]
// Tile 128x128, BK=32, 256 threads, 8 warps of 64x32.
// Register-prefetch double buffering: next chunk loads overlap current mmas.
// ---------------------------------------------------------------------------
__global__ __launch_bounds__(256) void gemm512_kernel(
    const float* __restrict__ X, const float* __restrict__ W,
    const float* __restrict__ bias, float* __restrict__ Y) {
    __shared__ uint32_t sA[128][36];
    __shared__ uint32_t sB[128][36];

    const int tid = threadIdx.x;
    const int lane = tid & 31;
    const int warp = tid >> 5;
    const int wR = warp >> 2;  // 0..1
    const int wC = warp & 3;   // 0..3
    const int row0 = blockIdx.y * 128;
    const int e0 = blockIdx.x * 128;

    const int lr = tid >> 3;         // 0..31 (row block of 4? no: see below)
    const int lc = (tid & 7) * 4;    // float4 col within 32-wide chunk

    float acc[4][4][4] = {};
    float4 ra[4], rb[4];

    // load chunk k0 into registers (each thread: 4 rows strided by 32)
    #pragma unroll
    for (int it = 0; it < 4; it++) {
        int r = lr + it * 32;
        ra[it] = *(const float4*)&X[(size_t)(row0 + r) * DD + 0 + lc];
        rb[it] = *(const float4*)&W[(size_t)(e0 + r) * DD + 0 + lc];
    }

    for (int k0 = 0; k0 < DD; k0 += 32) {
        #pragma unroll
        for (int it = 0; it < 4; it++) {
            int r = lr + it * 32;
            *(uint4*)&sA[r][lc] = f4totf(ra[it]);
            *(uint4*)&sB[r][lc] = f4totf(rb[it]);
        }
        __syncthreads();
        if (k0 + 32 < DD) {
            #pragma unroll
            for (int it = 0; it < 4; it++) {
                int r = lr + it * 32;
                ra[it] = *(const float4*)&X[(size_t)(row0 + r) * DD + k0 + 32 + lc];
                rb[it] = *(const float4*)&W[(size_t)(e0 + r) * DD + k0 + 32 + lc];
            }
        }
        #pragma unroll
        for (int kk = 0; kk < 32; kk += 8) {
            uint32_t af[4][4], bf[4][2];
            #pragma unroll
            for (int mt = 0; mt < 4; mt++) {
                int r = wR * 64 + mt * 16 + (lane >> 2);
                af[mt][0] = sA[r][kk + (lane & 3)];
                af[mt][1] = sA[r + 8][kk + (lane & 3)];
                af[mt][2] = sA[r][kk + 4 + (lane & 3)];
                af[mt][3] = sA[r + 8][kk + 4 + (lane & 3)];
            }
            #pragma unroll
            for (int nt = 0; nt < 4; nt++) {
                int c = wC * 32 + nt * 8 + (lane >> 2);
                bf[nt][0] = sB[c][kk + (lane & 3)];
                bf[nt][1] = sB[c][kk + 4 + (lane & 3)];
            }
            #pragma unroll
            for (int mt = 0; mt < 4; mt++)
                #pragma unroll
                for (int nt = 0; nt < 4; nt++) mma8(acc[mt][nt], af[mt], bf[nt]);
        }
        __syncthreads();
    }

    #pragma unroll
    for (int mt = 0; mt < 4; mt++) {
        int r = row0 + wR * 64 + mt * 16 + (lane >> 2);
        #pragma unroll
        for (int nt = 0; nt < 4; nt++) {
            int c = e0 + wC * 32 + nt * 8 + (lane & 3) * 2;
            float b0 = bias[c], b1 = bias[c + 1];
            *(float2*)&Y[(size_t)r * DD + c] =
                make_float2(acc[mt][nt][0] + b0, acc[mt][nt][1] + b1);
            *(float2*)&Y[(size_t)(r + 8) * DD + c] =
                make_float2(acc[mt][nt][2] + b0, acc[mt][nt][3] + b1);
        }
    }
}

// ---------------------------------------------------------------------------
// Zinv[b,n,m] = 1 / sum_h exp( (q_h(n).k_h(m)) / 8 )
// Tile 128x128, 512 threads, 16 warps of 32x32. BK=32, register prefetch.
// Flat loop over 16 k-chunks; fold exp at each head boundary (every 2 chunks).
// ---------------------------------------------------------------------------
__global__ __launch_bounds__(512) void zinv_kernel() {
    __shared__ uint32_t sQ[128][36];
    __shared__ uint32_t sK[128][36];

    const int tid = threadIdx.x;
    const int lane = tid & 31;
    const int warp = tid >> 5;
    const int wR = warp >> 2;  // 0..3
    const int wC = warp & 3;   // 0..3
    const int b = blockIdx.z;
    const int n0 = blockIdx.y * 128;
    const int m0 = blockIdx.x * 128;
    const float* Qp = g_Qp + (size_t)b * NN * DD;
    const float* Kp = g_Kp + (size_t)b * NN * DD;

    const int lr = tid >> 3;       // 0..63
    const int lc = (tid & 7) * 4;  // float4 col

    float z[2][4][4] = {};
    float dot[2][4][4] = {};
    float4 rq[2], rk[2];

    #pragma unroll
    for (int it = 0; it < 2; it++) {
        int r = lr + it * 64;
        rq[it] = *(const float4*)&Qp[(size_t)(n0 + r) * DD + lc];
        rk[it] = *(const float4*)&Kp[(size_t)(m0 + r) * DD + lc];
    }

    for (int ch = 0; ch < 16; ch++) {
        #pragma unroll
        for (int it = 0; it < 2; it++) {
            int r = lr + it * 64;
            *(uint4*)&sQ[r][lc] = f4totf(rq[it]);
            *(uint4*)&sK[r][lc] = f4totf(rk[it]);
        }
        __syncthreads();
        if (ch < 15) {
            int kb = (ch + 1) * 32;
            #pragma unroll
            for (int it = 0; it < 2; it++) {
                int r = lr + it * 64;
                rq[it] = *(const float4*)&Qp[(size_t)(n0 + r) * DD + kb + lc];
                rk[it] = *(const float4*)&Kp[(size_t)(m0 + r) * DD + kb + lc];
            }
        }
        #pragma unroll
        for (int kk = 0; kk < 32; kk += 8) {
            uint32_t af[2][4], bf[4][2];
            #pragma unroll
            for (int mt = 0; mt < 2; mt++) {
                int r = wR * 32 + mt * 16 + (lane >> 2);
                af[mt][0] = sQ[r][kk + (lane & 3)];
                af[mt][1] = sQ[r + 8][kk + (lane & 3)];
                af[mt][2] = sQ[r][kk + 4 + (lane & 3)];
                af[mt][3] = sQ[r + 8][kk + 4 + (lane & 3)];
            }
            #pragma unroll
            for (int nt = 0; nt < 4; nt++) {
                int c = wC * 32 + nt * 8 + (lane >> 2);
                bf[nt][0] = sK[c][kk + (lane & 3)];
                bf[nt][1] = sK[c][kk + 4 + (lane & 3)];
            }
            #pragma unroll
            for (int mt = 0; mt < 2; mt++)
                #pragma unroll
                for (int nt = 0; nt < 4; nt++) mma8(dot[mt][nt], af[mt], bf[nt]);
        }
        __syncthreads();
        if (ch & 1) {  // head boundary: fold exp, reset dot
            #pragma unroll
            for (int mt = 0; mt < 2; mt++)
                #pragma unroll
                for (int nt = 0; nt < 4; nt++)
                    #pragma unroll
                    for (int i = 0; i < 4; i++) {
                        z[mt][nt][i] += __expf(dot[mt][nt][i] * 0.125f);
                        dot[mt][nt][i] = 0.0f;
                    }
        }
    }

    #pragma unroll
    for (int mt = 0; mt < 2; mt++) {
        int r = n0 + wR * 32 + mt * 16 + (lane >> 2);
        #pragma unroll
        for (int nt = 0; nt < 4; nt++) {
            int c = m0 + wC * 32 + nt * 8 + (lane & 3) * 2;
            *(float2*)&g_Zinv[((size_t)b * NN + r) * NN + c] =
                make_float2(1.0f / z[mt][nt][0], 1.0f / z[mt][nt][1]);
            *(float2*)&g_Zinv[((size_t)b * NN + r + 8) * NN + c] =
                make_float2(1.0f / z[mt][nt][2], 1.0f / z[mt][nt][3]);
        }
    }
}

// ---------------------------------------------------------------------------
// Attention with precomputed Zinv. Per block: one (b,h,n-tile of 64).
// m-chunks of 64, 256 threads, 8 warps (2 row-bands x 4 col-bands).
// Dynamic smem (69.6 KB): sQ, sK, sVt, sP each 64x68 tf32 words.
// ---------------------------------------------------------------------------
#define ATTN_SMEM_WORDS (4 * 64 * 68)
#define ATTN_SMEM_BYTES (ATTN_SMEM_WORDS * 4)

__global__ __launch_bounds__(256) void attn_kernel() {
    extern __shared__ uint32_t smem[];
    uint32_t(*sQ)[68] = (uint32_t(*)[68])(smem);
    uint32_t(*sK)[68] = (uint32_t(*)[68])(smem + 64 * 68);
    uint32_t(*sVt)[68] = (uint32_t(*)[68])(smem + 2 * 64 * 68);
    uint32_t(*sP)[68] = (uint32_t(*)[68])(smem + 3 * 64 * 68);

    const int tid = threadIdx.x;
    const int lane = tid & 31;
    const int warp = tid >> 5;
    const int wR = warp >> 2;  // 0..1 (32-row band)
    const int wC = warp & 3;   // 0..3 (16-col band)
    const int b = blockIdx.z;
    const int h = blockIdx.y;
    const int n0 = blockIdx.x * 64;

    const float* Qp = g_Qp + (size_t)b * NN * DD + h * DKK;
    const float* Kp = g_Kp + (size_t)b * NN * DD + h * DKK;
    const float* Vp = g_Vp + (size_t)b * NN * DD + h * DKK;
    const float* Zb = g_Zinv + (size_t)b * NN * NN;

    // Load Q tile (64x64) once.
    #pragma unroll
    for (int it = 0; it < 4; it++) {
        int i = tid + it * 256;
        int r = i >> 4, c4 = (i & 15) * 4;
        float4 q = *(const float4*)&Qp[(size_t)(n0 + r) * DD + c4];
        *(uint4*)&sQ[r][c4] = f4totf(q);
    }

    // K/V stage mappings
    const int kr = tid >> 4;          // 0..15 base row; +16*it
    const int kc = (tid & 15) * 4;    // K float4 col
    const int vm = tid & 63;          // V: m (transposed store col)
    const int vd0 = (tid >> 6) * 4;   // V: d base; +16*it

    float4 rK[4], rV[4];
    #pragma unroll
    for (int it = 0; it < 4; it++) {
        rK[it] = *(const float4*)&Kp[(size_t)(kr + it * 16) * DD + kc];
        rV[it] = *(const float4*)&Vp[(size_t)vm * DD + vd0 + it * 16];
    }

    float accO[2][2][4] = {};

    for (int m0 = 0; m0 < NN; m0 += 64) {
        // store staged K/V chunk
        #pragma unroll
        for (int it = 0; it < 4; it++) {
            *(uint4*)&sK[kr + it * 16][kc] = f4totf(rK[it]);
            int dv = vd0 + it * 16;
            sVt[dv + 0][vm] = f2tf(rV[it].x);
            sVt[dv + 1][vm] = f2tf(rV[it].y);
            sVt[dv + 2][vm] = f2tf(rV[it].z);
            sVt[dv + 3][vm] = f2tf(rV[it].w);
        }
        __syncthreads();
        if (m0 + 64 < NN) {
            #pragma unroll
            for (int it = 0; it < 4; it++) {
                rK[it] = *(const float4*)&Kp[(size_t)(m0 + 64 + kr + it * 16) * DD + kc];
                rV[it] = *(const float4*)&Vp[(size_t)(m0 + 64 + vm) * DD + vd0 + it * 16];
            }
        }

        // ---- S = Q.K^T (64x64, contract 64) ----
        float accS[2][2][4] = {};
        #pragma unroll
        for (int kk = 0; kk < 64; kk += 8) {
            uint32_t af[2][4], bf[2][2];
            #pragma unroll
            for (int mt = 0; mt < 2; mt++) {
                int r = wR * 32 + mt * 16 + (lane >> 2);
                af[mt][0] = sQ[r][kk + (lane & 3)];
                af[mt][1] = sQ[r + 8][kk + (lane & 3)];
                af[mt][2] = sQ[r][kk + 4 + (lane & 3)];
                af[mt][3] = sQ[r + 8][kk + 4 + (lane & 3)];
            }
            #pragma unroll
            for (int nt = 0; nt < 2; nt++) {
                int c = wC * 16 + nt * 8 + (lane >> 2);
                bf[nt][0] = sK[c][kk + (lane & 3)];
                bf[nt][1] = sK[c][kk + 4 + (lane & 3)];
            }
            #pragma unroll
            for (int mt = 0; mt < 2; mt++)
                #pragma unroll
                for (int nt = 0; nt < 2; nt++) mma8(accS[mt][nt], af[mt], bf[nt]);
        }

        // P = exp(S/8) * Zinv -> sP (tf32)
        #pragma unroll
        for (int mt = 0; mt < 2; mt++) {
            int rl = wR * 32 + mt * 16 + (lane >> 2);
            #pragma unroll
            for (int nt = 0; nt < 2; nt++) {
                int cl = wC * 16 + nt * 8 + (lane & 3) * 2;
                float2 z0 = *(const float2*)&Zb[(size_t)(n0 + rl) * NN + m0 + cl];
                float2 z1 = *(const float2*)&Zb[(size_t)(n0 + rl + 8) * NN + m0 + cl];
                sP[rl][cl] = f2tf(__expf(accS[mt][nt][0] * 0.125f) * z0.x);
                sP[rl][cl + 1] = f2tf(__expf(accS[mt][nt][1] * 0.125f) * z0.y);
                sP[rl + 8][cl] = f2tf(__expf(accS[mt][nt][2] * 0.125f) * z1.x);
                sP[rl + 8][cl + 1] = f2tf(__expf(accS[mt][nt][3] * 0.125f) * z1.y);
            }
        }
        __syncthreads();

        // ---- O += P.V (64x64, contract 64) ----
        #pragma unroll
        for (int kk = 0; kk < 64; kk += 8) {
            uint32_t af[2][4], bf[2][2];
            #pragma unroll
            for (int mt = 0; mt < 2; mt++) {
                int r = wR * 32 + mt * 16 + (lane >> 2);
                af[mt][0] = sP[r][kk + (lane & 3)];
                af[mt][1] = sP[r + 8][kk + (lane & 3)];
                af[mt][2] = sP[r][kk + 4 + (lane & 3)];
                af[mt][3] = sP[r + 8][kk + 4 + (lane & 3)];
            }
            #pragma unroll
            for (int nt = 0; nt < 2; nt++) {
                int c = wC * 16 + nt * 8 + (lane >> 2);
                bf[nt][0] = sVt[c][kk + (lane & 3)];
                bf[nt][1] = sVt[c][kk + 4 + (lane & 3)];
            }
            #pragma unroll
            for (int mt = 0; mt < 2; mt++)
                #pragma unroll
                for (int nt = 0; nt < 2; nt++) mma8(accO[mt][nt], af[mt], bf[nt]);
        }
        __syncthreads();
    }

    #pragma unroll
    for (int mt = 0; mt < 2; mt++) {
        int r = n0 + wR * 32 + mt * 16 + (lane >> 2);
        #pragma unroll
        for (int nt = 0; nt < 2; nt++) {
            int c = h * DKK + wC * 16 + nt * 8 + (lane & 3) * 2;
            *(float2*)&g_A[((size_t)b * NN + r) * DD + c] =
                make_float2(accO[mt][nt][0], accO[mt][nt][1]);
            *(float2*)&g_A[((size_t)b * NN + r + 8) * DD + c] =
                make_float2(accO[mt][nt][2], accO[mt][nt][3]);
        }
    }
}

extern "C" void kernel_launch(void* const* d_in, const int* in_sizes, int n_in,
                              void* d_out, int out_size) {
    const float* Q = (const float*)d_in[0];
    const float* K = (const float*)d_in[1];
    const float* V = (const float*)d_in[2];
    const float* Wq = (const float*)d_in[3];
    const float* bq = (const float*)d_in[4];
    const float* Wo = (const float*)d_in[5];
    const float* bo = (const float*)d_in[6];
    float* out = (float*)d_out;

    void *pQp = nullptr, *pKp = nullptr, *pVp = nullptr, *pA = nullptr;
    cudaGetSymbolAddress(&pQp, g_Qp);
    cudaGetSymbolAddress(&pKp, g_Kp);
    cudaGetSymbolAddress(&pVp, g_Vp);
    cudaGetSymbolAddress(&pA, g_A);

    // Allow >48KB dynamic smem for attn (idempotent; set on pre-capture call).
    cudaFuncSetAttribute(attn_kernel, cudaFuncAttributeMaxDynamicSharedMemorySize,
                         ATTN_SMEM_BYTES);

    dim3 gGemm(DD / 128, (BB * NN) / 128);  // (4, 64)
    gemm512_kernel<<<gGemm, 256>>>(Q, Wq, bq, (float*)pQp);
    gemm512_kernel<<<gGemm, 256>>>(K, Wq, bq, (float*)pKp);
    gemm512_kernel<<<gGemm, 256>>>(V, Wq, bq, (float*)pVp);
    zinv_kernel<<<dim3(NN / 128, NN / 128, BB), 512>>>();
    attn_kernel<<<dim3(NN / 64, HH, BB), 256, ATTN_SMEM_BYTES>>>();
    gemm512_kernel<<<gGemm, 256>>>((const float*)pA, Wo, bo, out);
}

// round 8
// speedup vs baseline: 3.2781x; 1.0716x over previous
#include <cuda_runtime.h>
#include <math.h>
#include <stdint.h>

#define BB 4
#define NN 2048
#define DD 512
#define HH 8
#define DKK 64

__device__ float g_Qp[BB * NN * DD];
__device__ float g_Kp[BB * NN * DD];
__device__ float g_Vp[BB * NN * DD];
__device__ float g_Zinv[(size_t)BB * NN * NN];
__device__ float g_A[BB * NN * DD];

__device__ __forceinline__ uint32_t f2tf(float x) {
    uint32_t r;
    asm("cvt.rna.tf32.f32 %0, %1;" : "=r"(r) : "f"(x));
    return r;
}
__device__ __forceinline__ uint4 f4totf(float4 v) {
    return make_uint4(f2tf(v.x), f2tf(v.y), f2tf(v.z), f2tf(v.w));
}
__device__ __forceinline__ void mma8(float c[4], const uint32_t a[4],
                                     const uint32_t b[2]) {
    asm volatile(
        "mma.sync.aligned.m16n8k8.row.col.f32.tf32.tf32.f32 "
        "{%0,%1,%2,%3},{%4,%5,%6,%7},{%8,%9},{%0,%1,%2,%3};"
        : "+f"(c[0]), "+f"(c[1]), "+f"(c[2]), "+f"(c[3])
        : "r"(a[0]), "r"(a[1]), "r"(a[2]), "r"(a[3]), "r"(b[0]), "r"(b[1]));
}

// ---------------------------------------------------------------------------
// 512-K GEMM: Y[row,e] = sum_d X[row,d]*W[e,d] + bias[e]
// Tile 128x128, BK=32 (36-word rows, contraction <=32: in-bounds), 256 thr,
// 8 warps 64x32, register prefetch. blockIdx.z selects (X,Y) pair.
// ---------------------------------------------------------------------------
__global__ __launch_bounds__(256) void gemm512_kernel(
    const float* __restrict__ X0, const float* __restrict__ X1,
    const float* __restrict__ X2, const float* __restrict__ W,
    const float* __restrict__ bias, float* __restrict__ Y0,
    float* __restrict__ Y1, float* __restrict__ Y2) {
    const float* X = (blockIdx.z == 0) ? X0 : (blockIdx.z == 1) ? X1 : X2;
    float* Y = (blockIdx.z == 0) ? Y0 : (blockIdx.z == 1) ? Y1 : Y2;

    __shared__ uint32_t sA[128][36];
    __shared__ uint32_t sB[128][36];

    const int tid = threadIdx.x;
    const int lane = tid & 31;
    const int warp = tid >> 5;
    const int wR = warp >> 2;
    const int wC = warp & 3;
    const int row0 = blockIdx.y * 128;
    const int e0 = blockIdx.x * 128;

    const int lr = tid >> 3;
    const int lc = (tid & 7) * 4;

    float acc[4][4][4] = {};
    float4 ra[4], rb[4];

    #pragma unroll
    for (int it = 0; it < 4; it++) {
        int r = lr + it * 32;
        ra[it] = *(const float4*)&X[(size_t)(row0 + r) * DD + lc];
        rb[it] = *(const float4*)&W[(size_t)(e0 + r) * DD + lc];
    }

    for (int k0 = 0; k0 < DD; k0 += 32) {
        #pragma unroll
        for (int it = 0; it < 4; it++) {
            int r = lr + it * 32;
            *(uint4*)&sA[r][lc] = f4totf(ra[it]);
            *(uint4*)&sB[r][lc] = f4totf(rb[it]);
        }
        __syncthreads();
        if (k0 + 32 < DD) {
            #pragma unroll
            for (int it = 0; it < 4; it++) {
                int r = lr + it * 32;
                ra[it] = *(const float4*)&X[(size_t)(row0 + r) * DD + k0 + 32 + lc];
                rb[it] = *(const float4*)&W[(size_t)(e0 + r) * DD + k0 + 32 + lc];
            }
        }
        #pragma unroll
        for (int kk = 0; kk < 32; kk += 8) {
            uint32_t af[4][4], bf[4][2];
            #pragma unroll
            for (int mt = 0; mt < 4; mt++) {
                int r = wR * 64 + mt * 16 + (lane >> 2);
                af[mt][0] = sA[r][kk + (lane & 3)];
                af[mt][1] = sA[r + 8][kk + (lane & 3)];
                af[mt][2] = sA[r][kk + 4 + (lane & 3)];
                af[mt][3] = sA[r + 8][kk + 4 + (lane & 3)];
            }
            #pragma unroll
            for (int nt = 0; nt < 4; nt++) {
                int c = wC * 32 + nt * 8 + (lane >> 2);
                bf[nt][0] = sB[c][kk + (lane & 3)];
                bf[nt][1] = sB[c][kk + 4 + (lane & 3)];
            }
            #pragma unroll
            for (int mt = 0; mt < 4; mt++)
                #pragma unroll
                for (int nt = 0; nt < 4; nt++) mma8(acc[mt][nt], af[mt], bf[nt]);
        }
        __syncthreads();
    }

    #pragma unroll
    for (int mt = 0; mt < 4; mt++) {
        int r = row0 + wR * 64 + mt * 16 + (lane >> 2);
        #pragma unroll
        for (int nt = 0; nt < 4; nt++) {
            int c = e0 + wC * 32 + nt * 8 + (lane & 3) * 2;
            float b0 = bias[c], b1 = bias[c + 1];
            *(float2*)&Y[(size_t)r * DD + c] =
                make_float2(acc[mt][nt][0] + b0, acc[mt][nt][1] + b1);
            *(float2*)&Y[(size_t)(r + 8) * DD + c] =
                make_float2(acc[mt][nt][2] + b0, acc[mt][nt][3] + b1);
        }
    }
}

// ---------------------------------------------------------------------------
// Zinv[b,n,m] = 1 / sum_h exp( (q_h(n).k_h(m)) / 8 )
// Tile 128x128, 512 threads, 16 warps of 32x32. BK=32 (36-word rows).
// Double-buffered smem: ONE barrier per k-chunk.
// ---------------------------------------------------------------------------
#define ZINV_BUF_WORDS (2 * 128 * 36)
#define ZINV_SMEM_BYTES (2 * ZINV_BUF_WORDS * 4)

__global__ __launch_bounds__(512) void zinv_kernel() {
    extern __shared__ uint32_t zsm[];

    const int tid = threadIdx.x;
    const int lane = tid & 31;
    const int warp = tid >> 5;
    const int wR = warp >> 2;
    const int wC = warp & 3;
    const int b = blockIdx.z;
    const int n0 = blockIdx.y * 128;
    const int m0 = blockIdx.x * 128;
    const float* Qp = g_Qp + (size_t)b * NN * DD;
    const float* Kp = g_Kp + (size_t)b * NN * DD;

    const int lr = tid >> 3;       // 0..63
    const int lc = (tid & 7) * 4;  // 0..28

    float z[2][4][4] = {};
    float dot[2][4][4] = {};
    float4 rq[2], rk[2];

    {
        uint32_t(*sQ)[36] = (uint32_t(*)[36])(zsm);
        uint32_t(*sK)[36] = (uint32_t(*)[36])(zsm + 128 * 36);
        #pragma unroll
        for (int it = 0; it < 2; it++) {
            int r = lr + it * 64;
            *(uint4*)&sQ[r][lc] =
                f4totf(*(const float4*)&Qp[(size_t)(n0 + r) * DD + lc]);
            *(uint4*)&sK[r][lc] =
                f4totf(*(const float4*)&Kp[(size_t)(m0 + r) * DD + lc]);
        }
    }
    #pragma unroll
    for (int it = 0; it < 2; it++) {
        int r = lr + it * 64;
        rq[it] = *(const float4*)&Qp[(size_t)(n0 + r) * DD + 32 + lc];
        rk[it] = *(const float4*)&Kp[(size_t)(m0 + r) * DD + 32 + lc];
    }
    __syncthreads();

    for (int ch = 0; ch < 16; ch++) {
        if (ch < 15) {
            uint32_t* nb = zsm + ((ch + 1) & 1) * ZINV_BUF_WORDS;
            uint32_t(*sQn)[36] = (uint32_t(*)[36])(nb);
            uint32_t(*sKn)[36] = (uint32_t(*)[36])(nb + 128 * 36);
            #pragma unroll
            for (int it = 0; it < 2; it++) {
                int r = lr + it * 64;
                *(uint4*)&sQn[r][lc] = f4totf(rq[it]);
                *(uint4*)&sKn[r][lc] = f4totf(rk[it]);
            }
            if (ch < 14) {
                int kb = (ch + 2) * 32;
                #pragma unroll
                for (int it = 0; it < 2; it++) {
                    int r = lr + it * 64;
                    rq[it] = *(const float4*)&Qp[(size_t)(n0 + r) * DD + kb + lc];
                    rk[it] = *(const float4*)&Kp[(size_t)(m0 + r) * DD + kb + lc];
                }
            }
        }

        uint32_t* cb = zsm + (ch & 1) * ZINV_BUF_WORDS;
        uint32_t(*sQ)[36] = (uint32_t(*)[36])(cb);
        uint32_t(*sK)[36] = (uint32_t(*)[36])(cb + 128 * 36);

        #pragma unroll
        for (int kk = 0; kk < 32; kk += 8) {
            uint32_t af[2][4], bf[4][2];
            #pragma unroll
            for (int mt = 0; mt < 2; mt++) {
                int r = wR * 32 + mt * 16 + (lane >> 2);
                af[mt][0] = sQ[r][kk + (lane & 3)];
                af[mt][1] = sQ[r + 8][kk + (lane & 3)];
                af[mt][2] = sQ[r][kk + 4 + (lane & 3)];
                af[mt][3] = sQ[r + 8][kk + 4 + (lane & 3)];
            }
            #pragma unroll
            for (int nt = 0; nt < 4; nt++) {
                int c = wC * 32 + nt * 8 + (lane >> 2);
                bf[nt][0] = sK[c][kk + (lane & 3)];
                bf[nt][1] = sK[c][kk + 4 + (lane & 3)];
            }
            #pragma unroll
            for (int mt = 0; mt < 2; mt++)
                #pragma unroll
                for (int nt = 0; nt < 4; nt++) mma8(dot[mt][nt], af[mt], bf[nt]);
        }
        __syncthreads();

        if (ch & 1) {  // head boundary: fold exp
            #pragma unroll
            for (int mt = 0; mt < 2; mt++)
                #pragma unroll
                for (int nt = 0; nt < 4; nt++)
                    #pragma unroll
                    for (int i = 0; i < 4; i++) {
                        z[mt][nt][i] += __expf(dot[mt][nt][i] * 0.125f);
                        dot[mt][nt][i] = 0.0f;
                    }
        }
    }

    #pragma unroll
    for (int mt = 0; mt < 2; mt++) {
        int r = n0 + wR * 32 + mt * 16 + (lane >> 2);
        #pragma unroll
        for (int nt = 0; nt < 4; nt++) {
            int c = m0 + wC * 32 + nt * 8 + (lane & 3) * 2;
            *(float2*)&g_Zinv[((size_t)b * NN + r) * NN + c] =
                make_float2(1.0f / z[mt][nt][0], 1.0f / z[mt][nt][1]);
            *(float2*)&g_Zinv[((size_t)b * NN + r + 8) * NN + c] =
                make_float2(1.0f / z[mt][nt][2], 1.0f / z[mt][nt][3]);
        }
    }
}

// ---------------------------------------------------------------------------
// Attention with precomputed Zinv. Per block: (b, h, n-tile of 128).
// 256 threads, 8 warps as 4 row-bands x 2 col-bands (32x32 warp tiles).
// Contraction depth is 64 -> ALL rows use 68-word stride (kk up to 63).
// K/Vt double-buffered. Dynamic smem 139264 B, word layout (stride 68):
//   sQ[128] | sK0[64] sK1[64] | sVt0[64] sVt1[64] | sP[128]
// ---------------------------------------------------------------------------
#define ATTN_STRIDE 68
#define ATTN_SMEM_WORDS (512 * ATTN_STRIDE)
#define ATTN_SMEM_BYTES (ATTN_SMEM_WORDS * 4)

__global__ __launch_bounds__(256) void attn_kernel() {
    extern __shared__ uint32_t asm_[];
    uint32_t(*sQ)[ATTN_STRIDE] = (uint32_t(*)[ATTN_STRIDE])(asm_);
    uint32_t(*sP)[ATTN_STRIDE] =
        (uint32_t(*)[ATTN_STRIDE])(asm_ + 384 * ATTN_STRIDE);

    const int tid = threadIdx.x;
    const int lane = tid & 31;
    const int warp = tid >> 5;
    const int wR = warp >> 1;  // 0..3
    const int wC = warp & 1;   // 0..1
    const int b = blockIdx.z;
    const int h = blockIdx.y;
    const int n0 = blockIdx.x * 128;

    const float* Qp = g_Qp + (size_t)b * NN * DD + h * DKK;
    const float* Kp = g_Kp + (size_t)b * NN * DD + h * DKK;
    const float* Vp = g_Vp + (size_t)b * NN * DD + h * DKK;
    const float* Zb = g_Zinv + (size_t)b * NN * NN;

    // Q tile (128 x 64) once.
    #pragma unroll
    for (int it = 0; it < 8; it++) {
        int i = tid + it * 256;
        int r = i >> 4, c4 = (i & 15) * 4;
        *(uint4*)&sQ[r][c4] =
            f4totf(*(const float4*)&Qp[(size_t)(n0 + r) * DD + c4]);
    }

    const int kr = tid >> 4;         // 0..15; rows kr + 16*it
    const int kc = (tid & 15) * 4;   // 0..60
    const int vm = tid & 63;         // transposed store col
    const int vd0 = (tid >> 6) * 4;  // 0,4,8,12; rows vd0 + 16*it

    // Stage chunk 0 into buf0.
    {
        uint32_t(*sK)[ATTN_STRIDE] =
            (uint32_t(*)[ATTN_STRIDE])(asm_ + 128 * ATTN_STRIDE);
        uint32_t(*sVt)[ATTN_STRIDE] =
            (uint32_t(*)[ATTN_STRIDE])(asm_ + 256 * ATTN_STRIDE);
        #pragma unroll
        for (int it = 0; it < 4; it++) {
            *(uint4*)&sK[kr + it * 16][kc] =
                f4totf(*(const float4*)&Kp[(size_t)(kr + it * 16) * DD + kc]);
            int dv = vd0 + it * 16;
            float4 v4 = *(const float4*)&Vp[(size_t)vm * DD + dv];
            sVt[dv + 0][vm] = f2tf(v4.x);
            sVt[dv + 1][vm] = f2tf(v4.y);
            sVt[dv + 2][vm] = f2tf(v4.z);
            sVt[dv + 3][vm] = f2tf(v4.w);
        }
    }
    // Prefetch chunk 1.
    float4 rK[4], rV[4];
    #pragma unroll
    for (int it = 0; it < 4; it++) {
        rK[it] = *(const float4*)&Kp[(size_t)(64 + kr + it * 16) * DD + kc];
        rV[it] = *(const float4*)&Vp[(size_t)(64 + vm) * DD + vd0 + it * 16];
    }
    __syncthreads();

    float accO[2][4][4] = {};

    for (int c = 0; c < NN / 64; c++) {
        const int m0 = c * 64;
        if (c + 1 < NN / 64) {
            int nb = (c + 1) & 1;
            uint32_t(*sKn)[ATTN_STRIDE] =
                (uint32_t(*)[ATTN_STRIDE])(asm_ + (128 + nb * 64) * ATTN_STRIDE);
            uint32_t(*sVn)[ATTN_STRIDE] =
                (uint32_t(*)[ATTN_STRIDE])(asm_ + (256 + nb * 64) * ATTN_STRIDE);
            #pragma unroll
            for (int it = 0; it < 4; it++) {
                *(uint4*)&sKn[kr + it * 16][kc] = f4totf(rK[it]);
                int dv = vd0 + it * 16;
                sVn[dv + 0][vm] = f2tf(rV[it].x);
                sVn[dv + 1][vm] = f2tf(rV[it].y);
                sVn[dv + 2][vm] = f2tf(rV[it].z);
                sVn[dv + 3][vm] = f2tf(rV[it].w);
            }
            if (c + 2 < NN / 64) {
                int mb = m0 + 128;
                #pragma unroll
                for (int it = 0; it < 4; it++) {
                    rK[it] =
                        *(const float4*)&Kp[(size_t)(mb + kr + it * 16) * DD + kc];
                    rV[it] =
                        *(const float4*)&Vp[(size_t)(mb + vm) * DD + vd0 + it * 16];
                }
            }
        }

        int cbuf = c & 1;
        uint32_t(*sK)[ATTN_STRIDE] =
            (uint32_t(*)[ATTN_STRIDE])(asm_ + (128 + cbuf * 64) * ATTN_STRIDE);
        uint32_t(*sVt)[ATTN_STRIDE] =
            (uint32_t(*)[ATTN_STRIDE])(asm_ + (256 + cbuf * 64) * ATTN_STRIDE);

        // ---- S = Q.K^T (128x64, contract 64) ----
        float accS[2][4][4] = {};
        #pragma unroll
        for (int kk = 0; kk < 64; kk += 8) {
            uint32_t af[2][4], bf[4][2];
            #pragma unroll
            for (int mt = 0; mt < 2; mt++) {
                int r = wR * 32 + mt * 16 + (lane >> 2);
                af[mt][0] = sQ[r][kk + (lane & 3)];
                af[mt][1] = sQ[r + 8][kk + (lane & 3)];
                af[mt][2] = sQ[r][kk + 4 + (lane & 3)];
                af[mt][3] = sQ[r + 8][kk + 4 + (lane & 3)];
            }
            #pragma unroll
            for (int nt = 0; nt < 4; nt++) {
                int cc = wC * 32 + nt * 8 + (lane >> 2);
                bf[nt][0] = sK[cc][kk + (lane & 3)];
                bf[nt][1] = sK[cc][kk + 4 + (lane & 3)];
            }
            #pragma unroll
            for (int mt = 0; mt < 2; mt++)
                #pragma unroll
                for (int nt = 0; nt < 4; nt++) mma8(accS[mt][nt], af[mt], bf[nt]);
        }

        // P = exp(S/8) * Zinv -> sP
        #pragma unroll
        for (int mt = 0; mt < 2; mt++) {
            int rl = wR * 32 + mt * 16 + (lane >> 2);
            #pragma unroll
            for (int nt = 0; nt < 4; nt++) {
                int cl = wC * 32 + nt * 8 + (lane & 3) * 2;
                float2 z0 = *(const float2*)&Zb[(size_t)(n0 + rl) * NN + m0 + cl];
                float2 z1 =
                    *(const float2*)&Zb[(size_t)(n0 + rl + 8) * NN + m0 + cl];
                sP[rl][cl] = f2tf(__expf(accS[mt][nt][0] * 0.125f) * z0.x);
                sP[rl][cl + 1] = f2tf(__expf(accS[mt][nt][1] * 0.125f) * z0.y);
                sP[rl + 8][cl] = f2tf(__expf(accS[mt][nt][2] * 0.125f) * z1.x);
                sP[rl + 8][cl + 1] = f2tf(__expf(accS[mt][nt][3] * 0.125f) * z1.y);
            }
        }
        __syncthreads();

        // ---- O += P.V (128x64, contract 64) ----
        #pragma unroll
        for (int kk = 0; kk < 64; kk += 8) {
            uint32_t af[2][4], bf[4][2];
            #pragma unroll
            for (int mt = 0; mt < 2; mt++) {
                int r = wR * 32 + mt * 16 + (lane >> 2);
                af[mt][0] = sP[r][kk + (lane & 3)];
                af[mt][1] = sP[r + 8][kk + (lane & 3)];
                af[mt][2] = sP[r][kk + 4 + (lane & 3)];
                af[mt][3] = sP[r + 8][kk + 4 + (lane & 3)];
            }
            #pragma unroll
            for (int nt = 0; nt < 4; nt++) {
                int cc = wC * 32 + nt * 8 + (lane >> 2);
                bf[nt][0] = sVt[cc][kk + (lane & 3)];
                bf[nt][1] = sVt[cc][kk + 4 + (lane & 3)];
            }
            #pragma unroll
            for (int mt = 0; mt < 2; mt++)
                #pragma unroll
                for (int nt = 0; nt < 4; nt++) mma8(accO[mt][nt], af[mt], bf[nt]);
        }
        __syncthreads();
    }

    #pragma unroll
    for (int mt = 0; mt < 2; mt++) {
        int r = n0 + wR * 32 + mt * 16 + (lane >> 2);
        #pragma unroll
        for (int nt = 0; nt < 4; nt++) {
            int cc = h * DKK + wC * 32 + nt * 8 + (lane & 3) * 2;
            *(float2*)&g_A[((size_t)b * NN + r) * DD + cc] =
                make_float2(accO[mt][nt][0], accO[mt][nt][1]);
            *(float2*)&g_A[((size_t)b * NN + r + 8) * DD + cc] =
                make_float2(accO[mt][nt][2], accO[mt][nt][3]);
        }
    }
}

extern "C" void kernel_launch(void* const* d_in, const int* in_sizes, int n_in,
                              void* d_out, int out_size) {
    const float* Q = (const float*)d_in[0];
    const float* K = (const float*)d_in[1];
    const float* V = (const float*)d_in[2];
    const float* Wq = (const float*)d_in[3];
    const float* bq = (const float*)d_in[4];
    const float* Wo = (const float*)d_in[5];
    const float* bo = (const float*)d_in[6];
    float* out = (float*)d_out;

    void *pQp = nullptr, *pKp = nullptr, *pVp = nullptr, *pA = nullptr;
    cudaGetSymbolAddress(&pQp, g_Qp);
    cudaGetSymbolAddress(&pKp, g_Kp);
    cudaGetSymbolAddress(&pVp, g_Vp);
    cudaGetSymbolAddress(&pA, g_A);

    cudaFuncSetAttribute(zinv_kernel, cudaFuncAttributeMaxDynamicSharedMemorySize,
                         ZINV_SMEM_BYTES);
    cudaFuncSetAttribute(attn_kernel, cudaFuncAttributeMaxDynamicSharedMemorySize,
                         ATTN_SMEM_BYTES);

    dim3 gGemm(DD / 128, (BB * NN) / 128, 3);
    gemm512_kernel<<<gGemm, 256>>>(Q, K, V, Wq, bq, (float*)pQp, (float*)pKp,
                                   (float*)pVp);
    zinv_kernel<<<dim3(NN / 128, NN / 128, BB), 512, ZINV_SMEM_BYTES>>>();
    attn_kernel<<<dim3(NN / 128, HH, BB), 256, ATTN_SMEM_BYTES>>>();
    gemm512_kernel<<<dim3(DD / 128, (BB * NN) / 128, 1), 256>>>(
        (const float*)pA, nullptr, nullptr, Wo, bo, out, nullptr, nullptr);
}

// round 9
// speedup vs baseline: 3.3739x; 1.0292x over previous
#include <cuda_runtime.h>
#include <math.h>
#include <stdint.h>

#define BB 4
#define NN 2048
#define DD 512
#define HH 8
#define DKK 64

__device__ float g_Qp[BB * NN * DD];
__device__ float g_Kp[BB * NN * DD];
__device__ float g_Vp[BB * NN * DD];
__device__ float g_Zinv[(size_t)BB * NN * NN];
__device__ float g_A[BB * NN * DD];

__device__ __forceinline__ uint32_t f2tf(float x) {
    uint32_t r;
    asm("cvt.rna.tf32.f32 %0, %1;" : "=r"(r) : "f"(x));
    return r;
}
__device__ __forceinline__ uint4 f4totf(float4 v) {
    return make_uint4(f2tf(v.x), f2tf(v.y), f2tf(v.z), f2tf(v.w));
}
__device__ __forceinline__ void mma8(float c[4], const uint32_t a[4],
                                     const uint32_t b[2]) {
    asm volatile(
        "mma.sync.aligned.m16n8k8.row.col.f32.tf32.tf32.f32 "
        "{%0,%1,%2,%3},{%4,%5,%6,%7},{%8,%9},{%0,%1,%2,%3};"
        : "+f"(c[0]), "+f"(c[1]), "+f"(c[2]), "+f"(c[3])
        : "r"(a[0]), "r"(a[1]), "r"(a[2]), "r"(a[3]), "r"(b[0]), "r"(b[1]));
}
// One x4 ldmatrix: 4 8x8-b16 tiles == 4 8x4-tf32 chunks, lane l of each
// chunk holds (row l>>2, tf32col l&3) — exactly the m16n8k8 tf32 layout.
__device__ __forceinline__ void ldsm4(uint32_t r[4], uint32_t a) {
    asm volatile(
        "ldmatrix.sync.aligned.m8n8.x4.shared.b16 {%0,%1,%2,%3}, [%4];"
        : "=r"(r[0]), "=r"(r[1]), "=r"(r[2]), "=r"(r[3])
        : "r"(a));
}
__device__ __forceinline__ uint32_t smem_u32(const void* p) {
    return (uint32_t)__cvta_generic_to_shared(p);
}

// A-fragment lane terms: matrices {rows r..r+7 @kk, r+8..r+15 @kk,
// r..r+7 @kk+4, r+8.. @kk+4}  ->  row add ((lane>>3)&1)*8 + lane&7,
// col add (lane>>4)*4.
#define LANE_RA(lane) ((((lane) >> 3) & 1) * 8 + ((lane)&7))
#define LANE_CA(lane) (((lane) >> 4) * 4)
// B-pair lane terms: matrices {rows c..c+7 @kk, c..c+7 @kk+4,
// c+8..c+15 @kk, c+8.. @kk+4}.
#define LANE_RB(lane) ((((lane) >> 4)) * 8 + ((lane)&7))
#define LANE_CB(lane) ((((lane) >> 3) & 1) * 4)

// ---------------------------------------------------------------------------
// 512-K GEMM: Y[row,e] = sum_d X[row,d]*W[e,d] + bias[e]
// Tile 128x128, BK=32, 256 thr, 8 warps 64x32, register prefetch,
// ldmatrix fragment loads. blockIdx.z selects (X,Y) pair.
// ---------------------------------------------------------------------------
__global__ __launch_bounds__(256) void gemm512_kernel(
    const float* __restrict__ X0, const float* __restrict__ X1,
    const float* __restrict__ X2, const float* __restrict__ W,
    const float* __restrict__ bias, float* __restrict__ Y0,
    float* __restrict__ Y1, float* __restrict__ Y2) {
    const float* X = (blockIdx.z == 0) ? X0 : (blockIdx.z == 1) ? X1 : X2;
    float* Y = (blockIdx.z == 0) ? Y0 : (blockIdx.z == 1) ? Y1 : Y2;

    __shared__ uint32_t sA[128][36];
    __shared__ uint32_t sB[128][36];

    const int tid = threadIdx.x;
    const int lane = tid & 31;
    const int warp = tid >> 5;
    const int wR = warp >> 2;
    const int wC = warp & 3;
    const int row0 = blockIdx.y * 128;
    const int e0 = blockIdx.x * 128;

    const int lr = tid >> 3;
    const int lc = (tid & 7) * 4;

    const uint32_t aB = smem_u32(&sA[0][0]);
    const uint32_t bB = smem_u32(&sB[0][0]);
    const int rA = LANE_RA(lane), cA = LANE_CA(lane);
    const int rB = LANE_RB(lane), cB = LANE_CB(lane);

    float acc[4][4][4] = {};
    float4 ra[4], rb[4];

    #pragma unroll
    for (int it = 0; it < 4; it++) {
        int r = lr + it * 32;
        ra[it] = *(const float4*)&X[(size_t)(row0 + r) * DD + lc];
        rb[it] = *(const float4*)&W[(size_t)(e0 + r) * DD + lc];
    }

    for (int k0 = 0; k0 < DD; k0 += 32) {
        #pragma unroll
        for (int it = 0; it < 4; it++) {
            int r = lr + it * 32;
            *(uint4*)&sA[r][lc] = f4totf(ra[it]);
            *(uint4*)&sB[r][lc] = f4totf(rb[it]);
        }
        __syncthreads();
        if (k0 + 32 < DD) {
            #pragma unroll
            for (int it = 0; it < 4; it++) {
                int r = lr + it * 32;
                ra[it] = *(const float4*)&X[(size_t)(row0 + r) * DD + k0 + 32 + lc];
                rb[it] = *(const float4*)&W[(size_t)(e0 + r) * DD + k0 + 32 + lc];
            }
        }
        #pragma unroll
        for (int kk = 0; kk < 32; kk += 8) {
            uint32_t af[4][4], bp[2][4];
            #pragma unroll
            for (int mt = 0; mt < 4; mt++)
                ldsm4(af[mt],
                      aB + ((wR * 64 + mt * 16 + rA) * 36 + kk + cA) * 4);
            #pragma unroll
            for (int p = 0; p < 2; p++)
                ldsm4(bp[p],
                      bB + ((wC * 32 + p * 16 + rB) * 36 + kk + cB) * 4);
            #pragma unroll
            for (int mt = 0; mt < 4; mt++)
                #pragma unroll
                for (int nt = 0; nt < 4; nt++)
                    mma8(acc[mt][nt], af[mt], &bp[nt >> 1][(nt & 1) * 2]);
        }
        __syncthreads();
    }

    #pragma unroll
    for (int mt = 0; mt < 4; mt++) {
        int r = row0 + wR * 64 + mt * 16 + (lane >> 2);
        #pragma unroll
        for (int nt = 0; nt < 4; nt++) {
            int c = e0 + wC * 32 + nt * 8 + (lane & 3) * 2;
            float b0 = bias[c], b1 = bias[c + 1];
            *(float2*)&Y[(size_t)r * DD + c] =
                make_float2(acc[mt][nt][0] + b0, acc[mt][nt][1] + b1);
            *(float2*)&Y[(size_t)(r + 8) * DD + c] =
                make_float2(acc[mt][nt][2] + b0, acc[mt][nt][3] + b1);
        }
    }
}

// ---------------------------------------------------------------------------
// Zinv[b,n,m] = 1 / sum_h exp( (q_h(n).k_h(m)) / 8 )
// Tile 128x128, 512 threads, 16 warps of 32x32. BK=32, double-buffered,
// ldmatrix fragment loads.
// ---------------------------------------------------------------------------
#define ZINV_BUF_WORDS (2 * 128 * 36)
#define ZINV_SMEM_BYTES (2 * ZINV_BUF_WORDS * 4)

__global__ __launch_bounds__(512) void zinv_kernel() {
    extern __shared__ uint32_t zsm[];

    const int tid = threadIdx.x;
    const int lane = tid & 31;
    const int warp = tid >> 5;
    const int wR = warp >> 2;
    const int wC = warp & 3;
    const int b = blockIdx.z;
    const int n0 = blockIdx.y * 128;
    const int m0 = blockIdx.x * 128;
    const float* Qp = g_Qp + (size_t)b * NN * DD;
    const float* Kp = g_Kp + (size_t)b * NN * DD;

    const int lr = tid >> 3;
    const int lc = (tid & 7) * 4;

    const uint32_t base0 = smem_u32(zsm);
    const int rA = LANE_RA(lane), cA = LANE_CA(lane);
    const int rB = LANE_RB(lane), cB = LANE_CB(lane);

    float z[2][4][4] = {};
    float dot[2][4][4] = {};
    float4 rq[2], rk[2];

    {
        uint32_t(*sQ)[36] = (uint32_t(*)[36])(zsm);
        uint32_t(*sK)[36] = (uint32_t(*)[36])(zsm + 128 * 36);
        #pragma unroll
        for (int it = 0; it < 2; it++) {
            int r = lr + it * 64;
            *(uint4*)&sQ[r][lc] =
                f4totf(*(const float4*)&Qp[(size_t)(n0 + r) * DD + lc]);
            *(uint4*)&sK[r][lc] =
                f4totf(*(const float4*)&Kp[(size_t)(m0 + r) * DD + lc]);
        }
    }
    #pragma unroll
    for (int it = 0; it < 2; it++) {
        int r = lr + it * 64;
        rq[it] = *(const float4*)&Qp[(size_t)(n0 + r) * DD + 32 + lc];
        rk[it] = *(const float4*)&Kp[(size_t)(m0 + r) * DD + 32 + lc];
    }
    __syncthreads();

    for (int ch = 0; ch < 16; ch++) {
        if (ch < 15) {
            uint32_t* nb = zsm + ((ch + 1) & 1) * ZINV_BUF_WORDS;
            uint32_t(*sQn)[36] = (uint32_t(*)[36])(nb);
            uint32_t(*sKn)[36] = (uint32_t(*)[36])(nb + 128 * 36);
            #pragma unroll
            for (int it = 0; it < 2; it++) {
                int r = lr + it * 64;
                *(uint4*)&sQn[r][lc] = f4totf(rq[it]);
                *(uint4*)&sKn[r][lc] = f4totf(rk[it]);
            }
            if (ch < 14) {
                int kb = (ch + 2) * 32;
                #pragma unroll
                for (int it = 0; it < 2; it++) {
                    int r = lr + it * 64;
                    rq[it] = *(const float4*)&Qp[(size_t)(n0 + r) * DD + kb + lc];
                    rk[it] = *(const float4*)&Kp[(size_t)(m0 + r) * DD + kb + lc];
                }
            }
        }

        const uint32_t qB = base0 + (ch & 1) * (ZINV_BUF_WORDS * 4);
        const uint32_t kB = qB + 128 * 36 * 4;

        #pragma unroll
        for (int kk = 0; kk < 32; kk += 8) {
            uint32_t af[2][4], bp[2][4];
            #pragma unroll
            for (int mt = 0; mt < 2; mt++)
                ldsm4(af[mt],
                      qB + ((wR * 32 + mt * 16 + rA) * 36 + kk + cA) * 4);
            #pragma unroll
            for (int p = 0; p < 2; p++)
                ldsm4(bp[p],
                      kB + ((wC * 32 + p * 16 + rB) * 36 + kk + cB) * 4);
            #pragma unroll
            for (int mt = 0; mt < 2; mt++)
                #pragma unroll
                for (int nt = 0; nt < 4; nt++)
                    mma8(dot[mt][nt], af[mt], &bp[nt >> 1][(nt & 1) * 2]);
        }
        __syncthreads();

        if (ch & 1) {  // head boundary: fold exp
            #pragma unroll
            for (int mt = 0; mt < 2; mt++)
                #pragma unroll
                for (int nt = 0; nt < 4; nt++)
                    #pragma unroll
                    for (int i = 0; i < 4; i++) {
                        z[mt][nt][i] += __expf(dot[mt][nt][i] * 0.125f);
                        dot[mt][nt][i] = 0.0f;
                    }
        }
    }

    #pragma unroll
    for (int mt = 0; mt < 2; mt++) {
        int r = n0 + wR * 32 + mt * 16 + (lane >> 2);
        #pragma unroll
        for (int nt = 0; nt < 4; nt++) {
            int c = m0 + wC * 32 + nt * 8 + (lane & 3) * 2;
            *(float2*)&g_Zinv[((size_t)b * NN + r) * NN + c] =
                make_float2(1.0f / z[mt][nt][0], 1.0f / z[mt][nt][1]);
            *(float2*)&g_Zinv[((size_t)b * NN + r + 8) * NN + c] =
                make_float2(1.0f / z[mt][nt][2], 1.0f / z[mt][nt][3]);
        }
    }
}

// ---------------------------------------------------------------------------
// Attention with precomputed Zinv. Per block: (b, h, n-tile of 128).
// 256 threads, 8 warps 4x2 (32x32 warp tiles). Contraction 64, stride 68.
// K/Vt double-buffered, ldmatrix fragment loads. Dynamic smem 139264 B:
//   sQ[128] | sK0[64] sK1[64] | sVt0[64] sVt1[64] | sP[128]   (stride 68)
// ---------------------------------------------------------------------------
#define ATTN_STRIDE 68
#define ATTN_SMEM_WORDS (512 * ATTN_STRIDE)
#define ATTN_SMEM_BYTES (ATTN_SMEM_WORDS * 4)

__global__ __launch_bounds__(256) void attn_kernel() {
    extern __shared__ uint32_t asm_[];
    uint32_t(*sQ)[ATTN_STRIDE] = (uint32_t(*)[ATTN_STRIDE])(asm_);
    uint32_t(*sP)[ATTN_STRIDE] =
        (uint32_t(*)[ATTN_STRIDE])(asm_ + 384 * ATTN_STRIDE);

    const int tid = threadIdx.x;
    const int lane = tid & 31;
    const int warp = tid >> 5;
    const int wR = warp >> 1;  // 0..3
    const int wC = warp & 1;   // 0..1
    const int b = blockIdx.z;
    const int h = blockIdx.y;
    const int n0 = blockIdx.x * 128;

    const float* Qp = g_Qp + (size_t)b * NN * DD + h * DKK;
    const float* Kp = g_Kp + (size_t)b * NN * DD + h * DKK;
    const float* Vp = g_Vp + (size_t)b * NN * DD + h * DKK;
    const float* Zb = g_Zinv + (size_t)b * NN * NN;

    const uint32_t smB = smem_u32(asm_);
    const uint32_t qB = smB;
    const uint32_t pB = smB + 384 * ATTN_STRIDE * 4;
    const int rA = LANE_RA(lane), cA = LANE_CA(lane);
    const int rB = LANE_RB(lane), cB = LANE_CB(lane);

    // Q tile (128 x 64) once.
    #pragma unroll
    for (int it = 0; it < 8; it++) {
        int i = tid + it * 256;
        int r = i >> 4, c4 = (i & 15) * 4;
        *(uint4*)&sQ[r][c4] =
            f4totf(*(const float4*)&Qp[(size_t)(n0 + r) * DD + c4]);
    }

    const int kr = tid >> 4;
    const int kc = (tid & 15) * 4;
    const int vm = tid & 63;
    const int vd0 = (tid >> 6) * 4;

    {
        uint32_t(*sK)[ATTN_STRIDE] =
            (uint32_t(*)[ATTN_STRIDE])(asm_ + 128 * ATTN_STRIDE);
        uint32_t(*sVt)[ATTN_STRIDE] =
            (uint32_t(*)[ATTN_STRIDE])(asm_ + 256 * ATTN_STRIDE);
        #pragma unroll
        for (int it = 0; it < 4; it++) {
            *(uint4*)&sK[kr + it * 16][kc] =
                f4totf(*(const float4*)&Kp[(size_t)(kr + it * 16) * DD + kc]);
            int dv = vd0 + it * 16;
            float4 v4 = *(const float4*)&Vp[(size_t)vm * DD + dv];
            sVt[dv + 0][vm] = f2tf(v4.x);
            sVt[dv + 1][vm] = f2tf(v4.y);
            sVt[dv + 2][vm] = f2tf(v4.z);
            sVt[dv + 3][vm] = f2tf(v4.w);
        }
    }
    float4 rK[4], rV[4];
    #pragma unroll
    for (int it = 0; it < 4; it++) {
        rK[it] = *(const float4*)&Kp[(size_t)(64 + kr + it * 16) * DD + kc];
        rV[it] = *(const float4*)&Vp[(size_t)(64 + vm) * DD + vd0 + it * 16];
    }
    __syncthreads();

    float accO[2][4][4] = {};

    for (int c = 0; c < NN / 64; c++) {
        const int m0 = c * 64;
        if (c + 1 < NN / 64) {
            int nb = (c + 1) & 1;
            uint32_t(*sKn)[ATTN_STRIDE] =
                (uint32_t(*)[ATTN_STRIDE])(asm_ + (128 + nb * 64) * ATTN_STRIDE);
            uint32_t(*sVn)[ATTN_STRIDE] =
                (uint32_t(*)[ATTN_STRIDE])(asm_ + (256 + nb * 64) * ATTN_STRIDE);
            #pragma unroll
            for (int it = 0; it < 4; it++) {
                *(uint4*)&sKn[kr + it * 16][kc] = f4totf(rK[it]);
                int dv = vd0 + it * 16;
                sVn[dv + 0][vm] = f2tf(rV[it].x);
                sVn[dv + 1][vm] = f2tf(rV[it].y);
                sVn[dv + 2][vm] = f2tf(rV[it].z);
                sVn[dv + 3][vm] = f2tf(rV[it].w);
            }
            if (c + 2 < NN / 64) {
                int mb = m0 + 128;
                #pragma unroll
                for (int it = 0; it < 4; it++) {
                    rK[it] =
                        *(const float4*)&Kp[(size_t)(mb + kr + it * 16) * DD + kc];
                    rV[it] =
                        *(const float4*)&Vp[(size_t)(mb + vm) * DD + vd0 + it * 16];
                }
            }
        }

        int cbuf = c & 1;
        const uint32_t kB = smB + (128 + cbuf * 64) * ATTN_STRIDE * 4;
        const uint32_t vB = smB + (256 + cbuf * 64) * ATTN_STRIDE * 4;

        // ---- S = Q.K^T (128x64, contract 64) ----
        float accS[2][4][4] = {};
        #pragma unroll
        for (int kk = 0; kk < 64; kk += 8) {
            uint32_t af[2][4], bp[2][4];
            #pragma unroll
            for (int mt = 0; mt < 2; mt++)
                ldsm4(af[mt], qB + ((wR * 32 + mt * 16 + rA) * ATTN_STRIDE + kk +
                                    cA) * 4);
            #pragma unroll
            for (int p = 0; p < 2; p++)
                ldsm4(bp[p], kB + ((wC * 32 + p * 16 + rB) * ATTN_STRIDE + kk +
                                   cB) * 4);
            #pragma unroll
            for (int mt = 0; mt < 2; mt++)
                #pragma unroll
                for (int nt = 0; nt < 4; nt++)
                    mma8(accS[mt][nt], af[mt], &bp[nt >> 1][(nt & 1) * 2]);
        }

        // P = exp(S/8) * Zinv -> sP
        #pragma unroll
        for (int mt = 0; mt < 2; mt++) {
            int rl = wR * 32 + mt * 16 + (lane >> 2);
            #pragma unroll
            for (int nt = 0; nt < 4; nt++) {
                int cl = wC * 32 + nt * 8 + (lane & 3) * 2;
                float2 z0 = *(const float2*)&Zb[(size_t)(n0 + rl) * NN + m0 + cl];
                float2 z1 =
                    *(const float2*)&Zb[(size_t)(n0 + rl + 8) * NN + m0 + cl];
                sP[rl][cl] = f2tf(__expf(accS[mt][nt][0] * 0.125f) * z0.x);
                sP[rl][cl + 1] = f2tf(__expf(accS[mt][nt][1] * 0.125f) * z0.y);
                sP[rl + 8][cl] = f2tf(__expf(accS[mt][nt][2] * 0.125f) * z1.x);
                sP[rl + 8][cl + 1] = f2tf(__expf(accS[mt][nt][3] * 0.125f) * z1.y);
            }
        }
        __syncthreads();

        // ---- O += P.V (128x64, contract 64) ----
        #pragma unroll
        for (int kk = 0; kk < 64; kk += 8) {
            uint32_t af[2][4], bp[2][4];
            #pragma unroll
            for (int mt = 0; mt < 2; mt++)
                ldsm4(af[mt], pB + ((wR * 32 + mt * 16 + rA) * ATTN_STRIDE + kk +
                                    cA) * 4);
            #pragma unroll
            for (int p = 0; p < 2; p++)
                ldsm4(bp[p], vB + ((wC * 32 + p * 16 + rB) * ATTN_STRIDE + kk +
                                   cB) * 4);
            #pragma unroll
            for (int mt = 0; mt < 2; mt++)
                #pragma unroll
                for (int nt = 0; nt < 4; nt++)
                    mma8(accO[mt][nt], af[mt], &bp[nt >> 1][(nt & 1) * 2]);
        }
        __syncthreads();
    }

    #pragma unroll
    for (int mt = 0; mt < 2; mt++) {
        int r = n0 + wR * 32 + mt * 16 + (lane >> 2);
        #pragma unroll
        for (int nt = 0; nt < 4; nt++) {
            int cc = h * DKK + wC * 32 + nt * 8 + (lane & 3) * 2;
            *(float2*)&g_A[((size_t)b * NN + r) * DD + cc] =
                make_float2(accO[mt][nt][0], accO[mt][nt][1]);
            *(float2*)&g_A[((size_t)b * NN + r + 8) * DD + cc] =
                make_float2(accO[mt][nt][2], accO[mt][nt][3]);
        }
    }
}

extern "C" void kernel_launch(void* const* d_in, const int* in_sizes, int n_in,
                              void* d_out, int out_size) {
    const float* Q = (const float*)d_in[0];
    const float* K = (const float*)d_in[1];
    const float* V = (const float*)d_in[2];
    const float* Wq = (const float*)d_in[3];
    const float* bq = (const float*)d_in[4];
    const float* Wo = (const float*)d_in[5];
    const float* bo = (const float*)d_in[6];
    float* out = (float*)d_out;

    void *pQp = nullptr, *pKp = nullptr, *pVp = nullptr, *pA = nullptr;
    cudaGetSymbolAddress(&pQp, g_Qp);
    cudaGetSymbolAddress(&pKp, g_Kp);
    cudaGetSymbolAddress(&pVp, g_Vp);
    cudaGetSymbolAddress(&pA, g_A);

    cudaFuncSetAttribute(zinv_kernel, cudaFuncAttributeMaxDynamicSharedMemorySize,
                         ZINV_SMEM_BYTES);
    cudaFuncSetAttribute(attn_kernel, cudaFuncAttributeMaxDynamicSharedMemorySize,
                         ATTN_SMEM_BYTES);

    dim3 gGemm(DD / 128, (BB * NN) / 128, 3);
    gemm512_kernel<<<gGemm, 256>>>(Q, K, V, Wq, bq, (float*)pQp, (float*)pKp,
                                   (float*)pVp);
    zinv_kernel<<<dim3(NN / 128, NN / 128, BB), 512, ZINV_SMEM_BYTES>>>();
    attn_kernel<<<dim3(NN / 128, HH, BB), 256, ATTN_SMEM_BYTES>>>();
    gemm512_kernel<<<dim3(DD / 128, (BB * NN) / 128, 1), 256>>>(
        (const float*)pA, nullptr, nullptr, Wo, bo, out, nullptr, nullptr);
}

// round 11
// speedup vs baseline: 3.7456x; 1.1102x over previous
#include <cuda_runtime.h>
#include <math.h>
#include <stdint.h>

#define BB 4
#define NN 2048
#define DD 512
#define HH 8
#define DKK 64

__device__ float g_Qp[BB * NN * DD];
__device__ float g_Kp[BB * NN * DD];
__device__ float g_Vp[BB * NN * DD];
__device__ float g_Zinv[(size_t)BB * NN * NN];
__device__ float g_A[BB * NN * DD];

__device__ __forceinline__ uint32_t f2tf(float x) {
    uint32_t r;
    asm("cvt.rna.tf32.f32 %0, %1;" : "=r"(r) : "f"(x));
    return r;
}
__device__ __forceinline__ uint4 f4totf(float4 v) {
    return make_uint4(f2tf(v.x), f2tf(v.y), f2tf(v.z), f2tf(v.w));
}
__device__ __forceinline__ void mma8(float c[4], const uint32_t a[4],
                                     const uint32_t b[2]) {
    asm volatile(
        "mma.sync.aligned.m16n8k8.row.col.f32.tf32.tf32.f32 "
        "{%0,%1,%2,%3},{%4,%5,%6,%7},{%8,%9},{%0,%1,%2,%3};"
        : "+f"(c[0]), "+f"(c[1]), "+f"(c[2]), "+f"(c[3])
        : "r"(a[0]), "r"(a[1]), "r"(a[2]), "r"(a[3]), "r"(b[0]), "r"(b[1]));
}
__device__ __forceinline__ void ldsm4(uint32_t r[4], uint32_t a) {
    asm volatile(
        "ldmatrix.sync.aligned.m8n8.x4.shared.b16 {%0,%1,%2,%3}, [%4];"
        : "=r"(r[0]), "=r"(r[1]), "=r"(r[2]), "=r"(r[3])
        : "r"(a));
}
__device__ __forceinline__ uint32_t smem_u32(const void* p) {
    return (uint32_t)__cvta_generic_to_shared(p);
}

#define LANE_RA(lane) ((((lane) >> 3) & 1) * 8 + ((lane)&7))
#define LANE_CA(lane) (((lane) >> 4) * 4)
#define LANE_RB(lane) ((((lane) >> 4)) * 8 + ((lane)&7))
#define LANE_CB(lane) ((((lane) >> 3) & 1) * 4)

// ---------------------------------------------------------------------------
// 512-K GEMM: Y[row,e] = sum_d X[row,d]*W[e,d] + bias[e]
// Tile 128x128, BK=32, 256 thr (8 warps 64x32), register prefetch, ldmatrix.
// ---------------------------------------------------------------------------
__global__ __launch_bounds__(256, 2) void gemm512_kernel(
    const float* __restrict__ X0, const float* __restrict__ X1,
    const float* __restrict__ X2, const float* __restrict__ W,
    const float* __restrict__ bias, float* __restrict__ Y0,
    float* __restrict__ Y1, float* __restrict__ Y2) {
    const float* X = (blockIdx.z == 0) ? X0 : (blockIdx.z == 1) ? X1 : X2;
    float* Y = (blockIdx.z == 0) ? Y0 : (blockIdx.z == 1) ? Y1 : Y2;

    __shared__ uint32_t sA[128][36];
    __shared__ uint32_t sB[128][36];

    const int tid = threadIdx.x;
    const int lane = tid & 31;
    const int warp = tid >> 5;
    const int wR = warp >> 2;
    const int wC = warp & 3;
    const int row0 = blockIdx.y * 128;
    const int e0 = blockIdx.x * 128;

    const int lr = tid >> 3;
    const int lc = (tid & 7) * 4;

    const uint32_t aB = smem_u32(&sA[0][0]);
    const uint32_t bB = smem_u32(&sB[0][0]);
    const int rA = LANE_RA(lane), cA = LANE_CA(lane);
    const int rB = LANE_RB(lane), cB = LANE_CB(lane);

    float acc[4][4][4] = {};
    float4 ra[4], rb[4];

    #pragma unroll
    for (int it = 0; it < 4; it++) {
        int r = lr + it * 32;
        ra[it] = *(const float4*)&X[(size_t)(row0 + r) * DD + lc];
        rb[it] = *(const float4*)&W[(size_t)(e0 + r) * DD + lc];
    }

    for (int k0 = 0; k0 < DD; k0 += 32) {
        #pragma unroll
        for (int it = 0; it < 4; it++) {
            int r = lr + it * 32;
            *(uint4*)&sA[r][lc] = f4totf(ra[it]);
            *(uint4*)&sB[r][lc] = f4totf(rb[it]);
        }
        __syncthreads();
        if (k0 + 32 < DD) {
            #pragma unroll
            for (int it = 0; it < 4; it++) {
                int r = lr + it * 32;
                ra[it] = *(const float4*)&X[(size_t)(row0 + r) * DD + k0 + 32 + lc];
                rb[it] = *(const float4*)&W[(size_t)(e0 + r) * DD + k0 + 32 + lc];
            }
        }
        #pragma unroll
        for (int kk = 0; kk < 32; kk += 8) {
            uint32_t af[4][4], bp[2][4];
            #pragma unroll
            for (int mt = 0; mt < 4; mt++)
                ldsm4(af[mt],
                      aB + ((wR * 64 + mt * 16 + rA) * 36 + kk + cA) * 4);
            #pragma unroll
            for (int p = 0; p < 2; p++)
                ldsm4(bp[p],
                      bB + ((wC * 32 + p * 16 + rB) * 36 + kk + cB) * 4);
            #pragma unroll
            for (int mt = 0; mt < 4; mt++)
                #pragma unroll
                for (int nt = 0; nt < 4; nt++)
                    mma8(acc[mt][nt], af[mt], &bp[nt >> 1][(nt & 1) * 2]);
        }
        __syncthreads();
    }

    #pragma unroll
    for (int mt = 0; mt < 4; mt++) {
        int r = row0 + wR * 64 + mt * 16 + (lane >> 2);
        #pragma unroll
        for (int nt = 0; nt < 4; nt++) {
            int c = e0 + wC * 32 + nt * 8 + (lane & 3) * 2;
            float b0 = bias[c], b1 = bias[c + 1];
            *(float2*)&Y[(size_t)r * DD + c] =
                make_float2(acc[mt][nt][0] + b0, acc[mt][nt][1] + b1);
            *(float2*)&Y[(size_t)(r + 8) * DD + c] =
                make_float2(acc[mt][nt][2] + b0, acc[mt][nt][3] + b1);
        }
    }
}

// ---------------------------------------------------------------------------
// Zinv[b,n,m] = 1 / sum_h exp( (q_h(n).k_h(m)) / 8 )
// Tile 128x128, 512 threads, 16 warps of 32x32. BK=32, double-buffered,
// ldmatrix fragment loads.
// ---------------------------------------------------------------------------
#define ZINV_BUF_WORDS (2 * 128 * 36)
#define ZINV_SMEM_BYTES (2 * ZINV_BUF_WORDS * 4)

__global__ __launch_bounds__(512) void zinv_kernel() {
    extern __shared__ uint32_t zsm[];

    const int tid = threadIdx.x;
    const int lane = tid & 31;
    const int warp = tid >> 5;
    const int wR = warp >> 2;
    const int wC = warp & 3;
    const int b = blockIdx.z;
    const int n0 = blockIdx.y * 128;
    const int m0 = blockIdx.x * 128;
    const float* Qp = g_Qp + (size_t)b * NN * DD;
    const float* Kp = g_Kp + (size_t)b * NN * DD;

    const int lr = tid >> 3;
    const int lc = (tid & 7) * 4;

    const uint32_t base0 = smem_u32(zsm);
    const int rA = LANE_RA(lane), cA = LANE_CA(lane);
    const int rB = LANE_RB(lane), cB = LANE_CB(lane);

    float z[2][4][4] = {};
    float dot[2][4][4] = {};
    float4 rq[2], rk[2];

    {
        uint32_t(*sQ)[36] = (uint32_t(*)[36])(zsm);
        uint32_t(*sK)[36] = (uint32_t(*)[36])(zsm + 128 * 36);
        #pragma unroll
        for (int it = 0; it < 2; it++) {
            int r = lr + it * 64;
            *(uint4*)&sQ[r][lc] =
                f4totf(*(const float4*)&Qp[(size_t)(n0 + r) * DD + lc]);
            *(uint4*)&sK[r][lc] =
                f4totf(*(const float4*)&Kp[(size_t)(m0 + r) * DD + lc]);
        }
    }
    #pragma unroll
    for (int it = 0; it < 2; it++) {
        int r = lr + it * 64;
        rq[it] = *(const float4*)&Qp[(size_t)(n0 + r) * DD + 32 + lc];
        rk[it] = *(const float4*)&Kp[(size_t)(m0 + r) * DD + 32 + lc];
    }
    __syncthreads();

    for (int ch = 0; ch < 16; ch++) {
        if (ch < 15) {
            uint32_t* nb = zsm + ((ch + 1) & 1) * ZINV_BUF_WORDS;
            uint32_t(*sQn)[36] = (uint32_t(*)[36])(nb);
            uint32_t(*sKn)[36] = (uint32_t(*)[36])(nb + 128 * 36);
            #pragma unroll
            for (int it = 0; it < 2; it++) {
                int r = lr + it * 64;
                *(uint4*)&sQn[r][lc] = f4totf(rq[it]);
                *(uint4*)&sKn[r][lc] = f4totf(rk[it]);
            }
            if (ch < 14) {
                int kb = (ch + 2) * 32;
                #pragma unroll
                for (int it = 0; it < 2; it++) {
                    int r = lr + it * 64;
                    rq[it] = *(const float4*)&Qp[(size_t)(n0 + r) * DD + kb + lc];
                    rk[it] = *(const float4*)&Kp[(size_t)(m0 + r) * DD + kb + lc];
                }
            }
        }

        const uint32_t qB = base0 + (ch & 1) * (ZINV_BUF_WORDS * 4);
        const uint32_t kB = qB + 128 * 36 * 4;

        #pragma unroll
        for (int kk = 0; kk < 32; kk += 8) {
            uint32_t af[2][4], bp[2][4];
            #pragma unroll
            for (int mt = 0; mt < 2; mt++)
                ldsm4(af[mt],
                      qB + ((wR * 32 + mt * 16 + rA) * 36 + kk + cA) * 4);
            #pragma unroll
            for (int p = 0; p < 2; p++)
                ldsm4(bp[p],
                      kB + ((wC * 32 + p * 16 + rB) * 36 + kk + cB) * 4);
            #pragma unroll
            for (int mt = 0; mt < 2; mt++)
                #pragma unroll
                for (int nt = 0; nt < 4; nt++)
                    mma8(dot[mt][nt], af[mt], &bp[nt >> 1][(nt & 1) * 2]);
        }
        __syncthreads();

        if (ch & 1) {
            #pragma unroll
            for (int mt = 0; mt < 2; mt++)
                #pragma unroll
                for (int nt = 0; nt < 4; nt++)
                    #pragma unroll
                    for (int i = 0; i < 4; i++) {
                        z[mt][nt][i] += __expf(dot[mt][nt][i] * 0.125f);
                        dot[mt][nt][i] = 0.0f;
                    }
        }
    }

    #pragma unroll
    for (int mt = 0; mt < 2; mt++) {
        int r = n0 + wR * 32 + mt * 16 + (lane >> 2);
        #pragma unroll
        for (int nt = 0; nt < 4; nt++) {
            int c = m0 + wC * 32 + nt * 8 + (lane & 3) * 2;
            *(float2*)&g_Zinv[((size_t)b * NN + r) * NN + c] =
                make_float2(1.0f / z[mt][nt][0], 1.0f / z[mt][nt][1]);
            *(float2*)&g_Zinv[((size_t)b * NN + r + 8) * NN + c] =
                make_float2(1.0f / z[mt][nt][2], 1.0f / z[mt][nt][3]);
        }
    }
}

// ---------------------------------------------------------------------------
// Attention with precomputed Zinv. Per block: (b, h, n-tile of 128).
// 256 threads, 8 warps 4x2 (32x32 warp tiles). Contraction 64, stride 68.
// SINGLE-buffered K/Vt (2 CTAs/SM @ 104.4KB), 2 barriers per chunk:
//   S(c) [+Zinv(c) reg-prefetch] ; epi->sP ; syncA ;
//   PV(c) + K(c+1) gmem loads -> store sK ; syncB ; V(c+1) -> sVt.
// Smem rows (stride 68): sQ[0..127] | sK[128..191] | sVt[192..255] | sP[256..383]
// ---------------------------------------------------------------------------
#define ATTN_STRIDE 68
#define ATTN_SMEM_WORDS (384 * ATTN_STRIDE)
#define ATTN_SMEM_BYTES (ATTN_SMEM_WORDS * 4)

__global__ __launch_bounds__(256, 2) void attn_kernel() {
    extern __shared__ uint32_t asm_[];
    uint32_t(*sQ)[ATTN_STRIDE] = (uint32_t(*)[ATTN_STRIDE])(asm_);
    uint32_t(*sK)[ATTN_STRIDE] =
        (uint32_t(*)[ATTN_STRIDE])(asm_ + 128 * ATTN_STRIDE);
    uint32_t(*sVt)[ATTN_STRIDE] =
        (uint32_t(*)[ATTN_STRIDE])(asm_ + 192 * ATTN_STRIDE);
    uint32_t(*sP)[ATTN_STRIDE] =
        (uint32_t(*)[ATTN_STRIDE])(asm_ + 256 * ATTN_STRIDE);

    const int tid = threadIdx.x;
    const int lane = tid & 31;
    const int warp = tid >> 5;
    const int wR = warp >> 1;  // 0..3
    const int wC = warp & 1;   // 0..1
    const int b = blockIdx.z;
    const int h = blockIdx.y;
    const int n0 = blockIdx.x * 128;

    const float* Qp = g_Qp + (size_t)b * NN * DD + h * DKK;
    const float* Kp = g_Kp + (size_t)b * NN * DD + h * DKK;
    const float* Vp = g_Vp + (size_t)b * NN * DD + h * DKK;
    const float* Zb = g_Zinv + (size_t)b * NN * NN;

    const uint32_t smB = smem_u32(asm_);
    const uint32_t qB = smB;
    const uint32_t kB = smB + 128 * ATTN_STRIDE * 4;
    const uint32_t vB = smB + 192 * ATTN_STRIDE * 4;
    const uint32_t pB = smB + 256 * ATTN_STRIDE * 4;
    const int rA = LANE_RA(lane), cA = LANE_CA(lane);
    const int rB = LANE_RB(lane), cB = LANE_CB(lane);

    // Q tile (128 x 64) once.
    #pragma unroll
    for (int it = 0; it < 8; it++) {
        int i = tid + it * 256;
        int r = i >> 4, c4 = (i & 15) * 4;
        *(uint4*)&sQ[r][c4] =
            f4totf(*(const float4*)&Qp[(size_t)(n0 + r) * DD + c4]);
    }

    const int kr = tid >> 4;
    const int kc = (tid & 15) * 4;
    const int vm = tid & 63;
    const int vd0 = (tid >> 6) * 4;

    // Stage chunk 0.
    #pragma unroll
    for (int it = 0; it < 4; it++) {
        *(uint4*)&sK[kr + it * 16][kc] =
            f4totf(*(const float4*)&Kp[(size_t)(kr + it * 16) * DD + kc]);
        int dv = vd0 + it * 16;
        float4 v4 = *(const float4*)&Vp[(size_t)vm * DD + dv];
        sVt[dv + 0][vm] = f2tf(v4.x);
        sVt[dv + 1][vm] = f2tf(v4.y);
        sVt[dv + 2][vm] = f2tf(v4.z);
        sVt[dv + 3][vm] = f2tf(v4.w);
    }
    __syncthreads();

    // Per-thread epilogue row/col bases.
    const int erl = wR * 32 + (lane >> 2);          // +mt*16, +8
    const int ecl = wC * 32 + (lane & 3) * 2;       // +nt*8

    float accO[2][4][4] = {};

    for (int c = 0; c < NN / 64; c++) {
        const int m0 = c * 64;

        // Zinv(c) register prefetch — hidden behind the S mma phase.
        float2 rz[2][4][2];
        #pragma unroll
        for (int mt = 0; mt < 2; mt++)
            #pragma unroll
            for (int nt = 0; nt < 4; nt++) {
                int rl = erl + mt * 16, cl = ecl + nt * 8;
                rz[mt][nt][0] =
                    *(const float2*)&Zb[(size_t)(n0 + rl) * NN + m0 + cl];
                rz[mt][nt][1] =
                    *(const float2*)&Zb[(size_t)(n0 + rl + 8) * NN + m0 + cl];
            }

        // ---- S = Q.K^T (128x64, contract 64) ----
        float accS[2][4][4] = {};
        #pragma unroll
        for (int kk = 0; kk < 64; kk += 8) {
            uint32_t af[2][4], bp[2][4];
            #pragma unroll
            for (int mt = 0; mt < 2; mt++)
                ldsm4(af[mt], qB + ((wR * 32 + mt * 16 + rA) * ATTN_STRIDE + kk +
                                    cA) * 4);
            #pragma unroll
            for (int p = 0; p < 2; p++)
                ldsm4(bp[p], kB + ((wC * 32 + p * 16 + rB) * ATTN_STRIDE + kk +
                                   cB) * 4);
            #pragma unroll
            for (int mt = 0; mt < 2; mt++)
                #pragma unroll
                for (int nt = 0; nt < 4; nt++)
                    mma8(accS[mt][nt], af[mt], &bp[nt >> 1][(nt & 1) * 2]);
        }

        // P = exp(S/8) * Zinv -> sP
        #pragma unroll
        for (int mt = 0; mt < 2; mt++) {
            int rl = erl + mt * 16;
            #pragma unroll
            for (int nt = 0; nt < 4; nt++) {
                int cl = ecl + nt * 8;
                sP[rl][cl] = f2tf(__expf(accS[mt][nt][0] * 0.125f) * rz[mt][nt][0].x);
                sP[rl][cl + 1] =
                    f2tf(__expf(accS[mt][nt][1] * 0.125f) * rz[mt][nt][0].y);
                sP[rl + 8][cl] =
                    f2tf(__expf(accS[mt][nt][2] * 0.125f) * rz[mt][nt][1].x);
                sP[rl + 8][cl + 1] =
                    f2tf(__expf(accS[mt][nt][3] * 0.125f) * rz[mt][nt][1].y);
            }
        }
        __syncthreads();  // A: sP ready; sK(c) reads done

        // K(c+1) global loads — latency overlapped by the PV mma loop.
        float4 kt[4];
        const bool more = (c + 1 < NN / 64);
        if (more) {
            #pragma unroll
            for (int it = 0; it < 4; it++)
                kt[it] =
                    *(const float4*)&Kp[(size_t)(m0 + 64 + kr + it * 16) * DD + kc];
        }

        // ---- O += P.V (128x64, contract 64) ----
        #pragma unroll
        for (int kk = 0; kk < 64; kk += 8) {
            uint32_t af[2][4], bp[2][4];
            #pragma unroll
            for (int mt = 0; mt < 2; mt++)
                ldsm4(af[mt], pB + ((wR * 32 + mt * 16 + rA) * ATTN_STRIDE + kk +
                                    cA) * 4);
            #pragma unroll
            for (int p = 0; p < 2; p++)
                ldsm4(bp[p], vB + ((wC * 32 + p * 16 + rB) * ATTN_STRIDE + kk +
                                   cB) * 4);
            #pragma unroll
            for (int mt = 0; mt < 2; mt++)
                #pragma unroll
                for (int nt = 0; nt < 4; nt++)
                    mma8(accO[mt][nt], af[mt], &bp[nt >> 1][(nt & 1) * 2]);
        }

        // Store K(c+1) (sK(c) is dead: its reads ended before sync A).
        if (more) {
            #pragma unroll
            for (int it = 0; it < 4; it++)
                *(uint4*)&sK[kr + it * 16][kc] = f4totf(kt[it]);
        }
        __syncthreads();  // B: sVt(c)/sP reads done; sK(c+1) visible

        // V(c+1) load+store — store completes during the next S phase,
        // consumed only after the next sync A.
        if (more) {
            #pragma unroll
            for (int it = 0; it < 4; it++) {
                int dv = vd0 + it * 16;
                float4 v4 = *(const float4*)&Vp[(size_t)(m0 + 64 + vm) * DD + dv];
                sVt[dv + 0][vm] = f2tf(v4.x);
                sVt[dv + 1][vm] = f2tf(v4.y);
                sVt[dv + 2][vm] = f2tf(v4.z);
                sVt[dv + 3][vm] = f2tf(v4.w);
            }
        }
    }

    #pragma unroll
    for (int mt = 0; mt < 2; mt++) {
        int r = n0 + wR * 32 + mt * 16 + (lane >> 2);
        #pragma unroll
        for (int nt = 0; nt < 4; nt++) {
            int cc = h * DKK + wC * 32 + nt * 8 + (lane & 3) * 2;
            *(float2*)&g_A[((size_t)b * NN + r) * DD + cc] =
                make_float2(accO[mt][nt][0], accO[mt][nt][1]);
            *(float2*)&g_A[((size_t)b * NN + r + 8) * DD + cc] =
                make_float2(accO[mt][nt][2], accO[mt][nt][3]);
        }
    }
}

extern "C" void kernel_launch(void* const* d_in, const int* in_sizes, int n_in,
                              void* d_out, int out_size) {
    const float* Q = (const float*)d_in[0];
    const float* K = (const float*)d_in[1];
    const float* V = (const float*)d_in[2];
    const float* Wq = (const float*)d_in[3];
    const float* bq = (const float*)d_in[4];
    const float* Wo = (const float*)d_in[5];
    const float* bo = (const float*)d_in[6];
    float* out = (float*)d_out;

    void *pQp = nullptr, *pKp = nullptr, *pVp = nullptr, *pA = nullptr;
    cudaGetSymbolAddress(&pQp, g_Qp);
    cudaGetSymbolAddress(&pKp, g_Kp);
    cudaGetSymbolAddress(&pVp, g_Vp);
    cudaGetSymbolAddress(&pA, g_A);

    cudaFuncSetAttribute(zinv_kernel, cudaFuncAttributeMaxDynamicSharedMemorySize,
                         ZINV_SMEM_BYTES);
    cudaFuncSetAttribute(attn_kernel, cudaFuncAttributeMaxDynamicSharedMemorySize,
                         ATTN_SMEM_BYTES);

    dim3 gGemm(DD / 128, (BB * NN) / 128, 3);
    gemm512_kernel<<<gGemm, 256>>>(Q, K, V, Wq, bq, (float*)pQp, (float*)pKp,
                                   (float*)pVp);
    zinv_kernel<<<dim3(NN / 128, NN / 128, BB), 512, ZINV_SMEM_BYTES>>>();
    attn_kernel<<<dim3(NN / 128, HH, BB), 256, ATTN_SMEM_BYTES>>>();
    gemm512_kernel<<<dim3(DD / 128, (BB * NN) / 128, 1), 256>>>(
        (const float*)pA, nullptr, nullptr, Wo, bo, out, nullptr, nullptr);
}

// round 12
// speedup vs baseline: 5.1799x; 1.3829x over previous
#include <cuda_runtime.h>
#include <cuda_fp16.h>
#include <math.h>
#include <stdint.h>

#define BB 4
#define NN 2048
#define DD 512
#define HH 8
#define DKK 64

__device__ float g_Qp[BB * NN * DD];
__device__ float g_Kp[BB * NN * DD];
__device__ float g_Vp[BB * NN * DD];
__device__ float g_Zinv[(size_t)BB * NN * NN];
__device__ float g_A[BB * NN * DD];

// pack two floats -> half2 (lo = first arg)
__device__ __forceinline__ uint32_t f2h2(float lo, float hi) {
    uint32_t r;
    asm("cvt.rn.f16x2.f32 %0, %1, %2;" : "=r"(r) : "f"(hi), "f"(lo));
    return r;
}
__device__ __forceinline__ uint2 f4toh(float4 v) {
    return make_uint2(f2h2(v.x, v.y), f2h2(v.z, v.w));
}
__device__ __forceinline__ void mma16(float c[4], const uint32_t a[4],
                                      const uint32_t b[2]) {
    asm volatile(
        "mma.sync.aligned.m16n8k16.row.col.f32.f16.f16.f32 "
        "{%0,%1,%2,%3},{%4,%5,%6,%7},{%8,%9},{%0,%1,%2,%3};"
        : "+f"(c[0]), "+f"(c[1]), "+f"(c[2]), "+f"(c[3])
        : "r"(a[0]), "r"(a[1]), "r"(a[2]), "r"(a[3]), "r"(b[0]), "r"(b[1]));
}
__device__ __forceinline__ void ldsm4(uint32_t r[4], uint32_t a) {
    asm volatile(
        "ldmatrix.sync.aligned.m8n8.x4.shared.b16 {%0,%1,%2,%3}, [%4];"
        : "=r"(r[0]), "=r"(r[1]), "=r"(r[2]), "=r"(r[3])
        : "r"(a));
}
__device__ __forceinline__ uint32_t smem_u32(const void* p) {
    return (uint32_t)__cvta_generic_to_shared(p);
}

// A-tile (16x16 f16) ldmatrix lane mapping: row add + halfcol add
#define LANE_RA(lane) ((((lane) >> 3) & 1) * 8 + ((lane)&7))
#define LANE_HA(lane) (((lane) >> 4) * 8)
// B-pair (16n x 16k f16): row add + halfcol add
#define LANE_RB(lane) ((((lane) >> 4)) * 8 + ((lane)&7))
#define LANE_HB(lane) ((((lane) >> 3) & 1) * 8)

// ---------------------------------------------------------------------------
// 512-K GEMM (fp16 mma): Y[row,e] = sum_d X[row,d]*W[e,d] + bias[e]
// Tile 128x128, BK=32, 256 thr (8 warps 64x32), register prefetch, ldmatrix.
// smem rows: 32 halves, stride 20 u32 (80 B) — conflict-free ldsm.
// ---------------------------------------------------------------------------
#define GSTR 20

__global__ __launch_bounds__(256, 2) void gemm512_kernel(
    const float* __restrict__ X0, const float* __restrict__ X1,
    const float* __restrict__ X2, const float* __restrict__ W,
    const float* __restrict__ bias, float* __restrict__ Y0,
    float* __restrict__ Y1, float* __restrict__ Y2) {
    const float* X = (blockIdx.z == 0) ? X0 : (blockIdx.z == 1) ? X1 : X2;
    float* Y = (blockIdx.z == 0) ? Y0 : (blockIdx.z == 1) ? Y1 : Y2;

    __shared__ uint32_t sA[128][GSTR];
    __shared__ uint32_t sB[128][GSTR];

    const int tid = threadIdx.x;
    const int lane = tid & 31;
    const int warp = tid >> 5;
    const int wR = warp >> 2;
    const int wC = warp & 3;
    const int row0 = blockIdx.y * 128;
    const int e0 = blockIdx.x * 128;

    const int lr = tid >> 3;            // 0..31
    const int lcf = (tid & 7) * 4;      // float col
    const int lcu = (tid & 7) * 2;      // u32 col in smem

    const uint32_t aB = smem_u32(&sA[0][0]);
    const uint32_t bB = smem_u32(&sB[0][0]);
    const int rA = LANE_RA(lane), hA = LANE_HA(lane);
    const int rB = LANE_RB(lane), hB = LANE_HB(lane);

    float acc[4][4][4] = {};
    float4 ra[4], rb[4];

    #pragma unroll
    for (int it = 0; it < 4; it++) {
        int r = lr + it * 32;
        ra[it] = *(const float4*)&X[(size_t)(row0 + r) * DD + lcf];
        rb[it] = *(const float4*)&W[(size_t)(e0 + r) * DD + lcf];
    }

    for (int k0 = 0; k0 < DD; k0 += 32) {
        #pragma unroll
        for (int it = 0; it < 4; it++) {
            int r = lr + it * 32;
            *(uint2*)&sA[r][lcu] = f4toh(ra[it]);
            *(uint2*)&sB[r][lcu] = f4toh(rb[it]);
        }
        __syncthreads();
        if (k0 + 32 < DD) {
            #pragma unroll
            for (int it = 0; it < 4; it++) {
                int r = lr + it * 32;
                ra[it] = *(const float4*)&X[(size_t)(row0 + r) * DD + k0 + 32 + lcf];
                rb[it] = *(const float4*)&W[(size_t)(e0 + r) * DD + k0 + 32 + lcf];
            }
        }
        #pragma unroll
        for (int kk = 0; kk < 32; kk += 16) {
            uint32_t af[4][4], bp[2][4];
            #pragma unroll
            for (int mt = 0; mt < 4; mt++)
                ldsm4(af[mt], aB + (wR * 64 + mt * 16 + rA) * (GSTR * 4) +
                                  (kk + hA) * 2);
            #pragma unroll
            for (int p = 0; p < 2; p++)
                ldsm4(bp[p], bB + (wC * 32 + p * 16 + rB) * (GSTR * 4) +
                                 (kk + hB) * 2);
            #pragma unroll
            for (int mt = 0; mt < 4; mt++)
                #pragma unroll
                for (int nt = 0; nt < 4; nt++)
                    mma16(acc[mt][nt], af[mt], &bp[nt >> 1][(nt & 1) * 2]);
        }
        __syncthreads();
    }

    #pragma unroll
    for (int mt = 0; mt < 4; mt++) {
        int r = row0 + wR * 64 + mt * 16 + (lane >> 2);
        #pragma unroll
        for (int nt = 0; nt < 4; nt++) {
            int c = e0 + wC * 32 + nt * 8 + (lane & 3) * 2;
            float b0 = bias[c], b1 = bias[c + 1];
            *(float2*)&Y[(size_t)r * DD + c] =
                make_float2(acc[mt][nt][0] + b0, acc[mt][nt][1] + b1);
            *(float2*)&Y[(size_t)(r + 8) * DD + c] =
                make_float2(acc[mt][nt][2] + b0, acc[mt][nt][3] + b1);
        }
    }
}

// ---------------------------------------------------------------------------
// Zinv[b,n,m] = 1 / sum_h exp( (q_h(n).k_h(m)) / 8 )   (fp16 mma)
// Tile 128x128, 512 threads, 16 warps 32x32. BK=32, double-buffered.
// ---------------------------------------------------------------------------
#define ZINV_BUF_WORDS (2 * 128 * GSTR)
#define ZINV_SMEM_BYTES (2 * ZINV_BUF_WORDS * 4)

__global__ __launch_bounds__(512) void zinv_kernel() {
    extern __shared__ uint32_t zsm[];

    const int tid = threadIdx.x;
    const int lane = tid & 31;
    const int warp = tid >> 5;
    const int wR = warp >> 2;
    const int wC = warp & 3;
    const int b = blockIdx.z;
    const int n0 = blockIdx.y * 128;
    const int m0 = blockIdx.x * 128;
    const float* Qp = g_Qp + (size_t)b * NN * DD;
    const float* Kp = g_Kp + (size_t)b * NN * DD;

    const int lr = tid >> 3;        // 0..63
    const int lcf = (tid & 7) * 4;
    const int lcu = (tid & 7) * 2;

    const uint32_t base0 = smem_u32(zsm);
    const int rA = LANE_RA(lane), hA = LANE_HA(lane);
    const int rB = LANE_RB(lane), hB = LANE_HB(lane);

    float z[2][4][4] = {};
    float dot[2][4][4] = {};
    float4 rq[2], rk[2];

    {
        uint32_t(*sQ)[GSTR] = (uint32_t(*)[GSTR])(zsm);
        uint32_t(*sK)[GSTR] = (uint32_t(*)[GSTR])(zsm + 128 * GSTR);
        #pragma unroll
        for (int it = 0; it < 2; it++) {
            int r = lr + it * 64;
            *(uint2*)&sQ[r][lcu] =
                f4toh(*(const float4*)&Qp[(size_t)(n0 + r) * DD + lcf]);
            *(uint2*)&sK[r][lcu] =
                f4toh(*(const float4*)&Kp[(size_t)(m0 + r) * DD + lcf]);
        }
    }
    #pragma unroll
    for (int it = 0; it < 2; it++) {
        int r = lr + it * 64;
        rq[it] = *(const float4*)&Qp[(size_t)(n0 + r) * DD + 32 + lcf];
        rk[it] = *(const float4*)&Kp[(size_t)(m0 + r) * DD + 32 + lcf];
    }
    __syncthreads();

    for (int ch = 0; ch < 16; ch++) {
        if (ch < 15) {
            uint32_t* nb = zsm + ((ch + 1) & 1) * ZINV_BUF_WORDS;
            uint32_t(*sQn)[GSTR] = (uint32_t(*)[GSTR])(nb);
            uint32_t(*sKn)[GSTR] = (uint32_t(*)[GSTR])(nb + 128 * GSTR);
            #pragma unroll
            for (int it = 0; it < 2; it++) {
                int r = lr + it * 64;
                *(uint2*)&sQn[r][lcu] = f4toh(rq[it]);
                *(uint2*)&sKn[r][lcu] = f4toh(rk[it]);
            }
            if (ch < 14) {
                int kb = (ch + 2) * 32;
                #pragma unroll
                for (int it = 0; it < 2; it++) {
                    int r = lr + it * 64;
                    rq[it] = *(const float4*)&Qp[(size_t)(n0 + r) * DD + kb + lcf];
                    rk[it] = *(const float4*)&Kp[(size_t)(m0 + r) * DD + kb + lcf];
                }
            }
        }

        const uint32_t qB = base0 + (ch & 1) * (ZINV_BUF_WORDS * 4);
        const uint32_t kB = qB + 128 * GSTR * 4;

        #pragma unroll
        for (int kk = 0; kk < 32; kk += 16) {
            uint32_t af[2][4], bp[2][4];
            #pragma unroll
            for (int mt = 0; mt < 2; mt++)
                ldsm4(af[mt], qB + (wR * 32 + mt * 16 + rA) * (GSTR * 4) +
                                  (kk + hA) * 2);
            #pragma unroll
            for (int p = 0; p < 2; p++)
                ldsm4(bp[p], kB + (wC * 32 + p * 16 + rB) * (GSTR * 4) +
                                 (kk + hB) * 2);
            #pragma unroll
            for (int mt = 0; mt < 2; mt++)
                #pragma unroll
                for (int nt = 0; nt < 4; nt++)
                    mma16(dot[mt][nt], af[mt], &bp[nt >> 1][(nt & 1) * 2]);
        }
        __syncthreads();

        if (ch & 1) {  // head boundary: fold exp
            #pragma unroll
            for (int mt = 0; mt < 2; mt++)
                #pragma unroll
                for (int nt = 0; nt < 4; nt++)
                    #pragma unroll
                    for (int i = 0; i < 4; i++) {
                        z[mt][nt][i] += __expf(dot[mt][nt][i] * 0.125f);
                        dot[mt][nt][i] = 0.0f;
                    }
        }
    }

    #pragma unroll
    for (int mt = 0; mt < 2; mt++) {
        int r = n0 + wR * 32 + mt * 16 + (lane >> 2);
        #pragma unroll
        for (int nt = 0; nt < 4; nt++) {
            int c = m0 + wC * 32 + nt * 8 + (lane & 3) * 2;
            *(float2*)&g_Zinv[((size_t)b * NN + r) * NN + c] =
                make_float2(1.0f / z[mt][nt][0], 1.0f / z[mt][nt][1]);
            *(float2*)&g_Zinv[((size_t)b * NN + r + 8) * NN + c] =
                make_float2(1.0f / z[mt][nt][2], 1.0f / z[mt][nt][3]);
        }
    }
}

// ---------------------------------------------------------------------------
// Attention with precomputed Zinv (fp16 mma). Per block: (b,h,n-tile 128).
// 256 threads, 8 warps 4x2 (32x32 warp tiles). Contraction 64 halves,
// stride 36 u32 (144 B) per row. Same 2-barrier schedule as R11.
// Smem rows: sQ[0..127] | sK[128..191] | sVt[192..255] | sP[256..383]
// = 384*36*4 = 55296 B -> 2 CTAs/SM.
// ---------------------------------------------------------------------------
#define ASTR 36
#define ATTN_SMEM_WORDS (384 * ASTR)
#define ATTN_SMEM_BYTES (ATTN_SMEM_WORDS * 4)

__global__ __launch_bounds__(256, 2) void attn_kernel() {
    extern __shared__ uint32_t asm_[];
    uint32_t(*sQ)[ASTR] = (uint32_t(*)[ASTR])(asm_);
    uint32_t(*sK)[ASTR] = (uint32_t(*)[ASTR])(asm_ + 128 * ASTR);
    __half* hV = (__half*)(asm_ + 192 * ASTR);  // rows of 72 halves
    uint32_t(*sP)[ASTR] = (uint32_t(*)[ASTR])(asm_ + 256 * ASTR);

    const int tid = threadIdx.x;
    const int lane = tid & 31;
    const int warp = tid >> 5;
    const int wR = warp >> 1;  // 0..3
    const int wC = warp & 1;   // 0..1
    const int b = blockIdx.z;
    const int h = blockIdx.y;
    const int n0 = blockIdx.x * 128;

    const float* Qp = g_Qp + (size_t)b * NN * DD + h * DKK;
    const float* Kp = g_Kp + (size_t)b * NN * DD + h * DKK;
    const float* Vp = g_Vp + (size_t)b * NN * DD + h * DKK;
    const float* Zb = g_Zinv + (size_t)b * NN * NN;

    const uint32_t smB = smem_u32(asm_);
    const uint32_t qB = smB;
    const uint32_t kB = smB + 128 * ASTR * 4;
    const uint32_t vB = smB + 192 * ASTR * 4;
    const uint32_t pB = smB + 256 * ASTR * 4;
    const int rA = LANE_RA(lane), hA = LANE_HA(lane);
    const int rB = LANE_RB(lane), hB = LANE_HB(lane);

    // Q tile (128 x 64 halves) once.
    #pragma unroll
    for (int it = 0; it < 8; it++) {
        int i = tid + it * 256;
        int r = i >> 4, cf = (i & 15) * 4;
        *(uint2*)&sQ[r][(i & 15) * 2] =
            f4toh(*(const float4*)&Qp[(size_t)(n0 + r) * DD + cf]);
    }

    const int kr = tid >> 4;          // 0..15
    const int kcf = (tid & 15) * 4;   // float col
    const int kcu = (tid & 15) * 2;   // u32 col
    const int vm = tid & 63;
    const int vd0 = (tid >> 6) * 4;

    // Stage chunk 0.
    #pragma unroll
    for (int it = 0; it < 4; it++) {
        *(uint2*)&sK[kr + it * 16][kcu] =
            f4toh(*(const float4*)&Kp[(size_t)(kr + it * 16) * DD + kcf]);
        int dv = vd0 + it * 16;
        float4 v4 = *(const float4*)&Vp[(size_t)vm * DD + dv];
        hV[(dv + 0) * 72 + vm] = __float2half_rn(v4.x);
        hV[(dv + 1) * 72 + vm] = __float2half_rn(v4.y);
        hV[(dv + 2) * 72 + vm] = __float2half_rn(v4.z);
        hV[(dv + 3) * 72 + vm] = __float2half_rn(v4.w);
    }
    __syncthreads();

    const int erl = wR * 32 + (lane >> 2);     // +mt*16, +8
    const int ecl = wC * 32 + (lane & 3) * 2;  // +nt*8

    float accO[2][4][4] = {};

    for (int c = 0; c < NN / 64; c++) {
        const int m0 = c * 64;

        // Zinv(c) register prefetch — hidden behind the S mma phase.
        float2 rz[2][4][2];
        #pragma unroll
        for (int mt = 0; mt < 2; mt++)
            #pragma unroll
            for (int nt = 0; nt < 4; nt++) {
                int rl = erl + mt * 16, cl = ecl + nt * 8;
                rz[mt][nt][0] =
                    *(const float2*)&Zb[(size_t)(n0 + rl) * NN + m0 + cl];
                rz[mt][nt][1] =
                    *(const float2*)&Zb[(size_t)(n0 + rl + 8) * NN + m0 + cl];
            }

        // ---- S = Q.K^T (128x64, contract 64) ----
        float accS[2][4][4] = {};
        #pragma unroll
        for (int kk = 0; kk < 64; kk += 16) {
            uint32_t af[2][4], bp[2][4];
            #pragma unroll
            for (int mt = 0; mt < 2; mt++)
                ldsm4(af[mt], qB + (wR * 32 + mt * 16 + rA) * (ASTR * 4) +
                                  (kk + hA) * 2);
            #pragma unroll
            for (int p = 0; p < 2; p++)
                ldsm4(bp[p], kB + (wC * 32 + p * 16 + rB) * (ASTR * 4) +
                                 (kk + hB) * 2);
            #pragma unroll
            for (int mt = 0; mt < 2; mt++)
                #pragma unroll
                for (int nt = 0; nt < 4; nt++)
                    mma16(accS[mt][nt], af[mt], &bp[nt >> 1][(nt & 1) * 2]);
        }

        // P = exp(S/8) * Zinv -> sP (half2 packed)
        #pragma unroll
        for (int mt = 0; mt < 2; mt++) {
            int rl = erl + mt * 16;
            #pragma unroll
            for (int nt = 0; nt < 4; nt++) {
                int cu = wC * 16 + nt * 4 + (lane & 3);  // u32 col = cl>>1
                sP[rl][cu] =
                    f2h2(__expf(accS[mt][nt][0] * 0.125f) * rz[mt][nt][0].x,
                         __expf(accS[mt][nt][1] * 0.125f) * rz[mt][nt][0].y);
                sP[rl + 8][cu] =
                    f2h2(__expf(accS[mt][nt][2] * 0.125f) * rz[mt][nt][1].x,
                         __expf(accS[mt][nt][3] * 0.125f) * rz[mt][nt][1].y);
            }
        }
        __syncthreads();  // A: sP ready; sK(c) reads done

        // K(c+1) global loads — hidden behind the PV mma loop.
        float4 kt[4];
        const bool more = (c + 1 < NN / 64);
        if (more) {
            #pragma unroll
            for (int it = 0; it < 4; it++)
                kt[it] =
                    *(const float4*)&Kp[(size_t)(m0 + 64 + kr + it * 16) * DD + kcf];
        }

        // ---- O += P.V (128x64, contract 64) ----
        #pragma unroll
        for (int kk = 0; kk < 64; kk += 16) {
            uint32_t af[2][4], bp[2][4];
            #pragma unroll
            for (int mt = 0; mt < 2; mt++)
                ldsm4(af[mt], pB + (wR * 32 + mt * 16 + rA) * (ASTR * 4) +
                                  (kk + hA) * 2);
            #pragma unroll
            for (int p = 0; p < 2; p++)
                ldsm4(bp[p], vB + (wC * 32 + p * 16 + rB) * (ASTR * 4) +
                                 (kk + hB) * 2);
            #pragma unroll
            for (int mt = 0; mt < 2; mt++)
                #pragma unroll
                for (int nt = 0; nt < 4; nt++)
                    mma16(accO[mt][nt], af[mt], &bp[nt >> 1][(nt & 1) * 2]);
        }

        // Store K(c+1) (sK(c) dead since sync A).
        if (more) {
            #pragma unroll
            for (int it = 0; it < 4; it++)
                *(uint2*)&sK[kr + it * 16][kcu] = f4toh(kt[it]);
        }
        __syncthreads();  // B: sVt/sP reads done; sK(c+1) visible

        // V(c+1) -> sVt (consumed after next sync A).
        if (more) {
            #pragma unroll
            for (int it = 0; it < 4; it++) {
                int dv = vd0 + it * 16;
                float4 v4 = *(const float4*)&Vp[(size_t)(m0 + 64 + vm) * DD + dv];
                hV[(dv + 0) * 72 + vm] = __float2half_rn(v4.x);
                hV[(dv + 1) * 72 + vm] = __float2half_rn(v4.y);
                hV[(dv + 2) * 72 + vm] = __float2half_rn(v4.z);
                hV[(dv + 3) * 72 + vm] = __float2half_rn(v4.w);
            }
        }
    }

    #pragma unroll
    for (int mt = 0; mt < 2; mt++) {
        int r = n0 + wR * 32 + mt * 16 + (lane >> 2);
        #pragma unroll
        for (int nt = 0; nt < 4; nt++) {
            int cc = h * DKK + wC * 32 + nt * 8 + (lane & 3) * 2;
            *(float2*)&g_A[((size_t)b * NN + r) * DD + cc] =
                make_float2(accO[mt][nt][0], accO[mt][nt][1]);
            *(float2*)&g_A[((size_t)b * NN + r + 8) * DD + cc] =
                make_float2(accO[mt][nt][2], accO[mt][nt][3]);
        }
    }
}

extern "C" void kernel_launch(void* const* d_in, const int* in_sizes, int n_in,
                              void* d_out, int out_size) {
    const float* Q = (const float*)d_in[0];
    const float* K = (const float*)d_in[1];
    const float* V = (const float*)d_in[2];
    const float* Wq = (const float*)d_in[3];
    const float* bq = (const float*)d_in[4];
    const float* Wo = (const float*)d_in[5];
    const float* bo = (const float*)d_in[6];
    float* out = (float*)d_out;

    void *pQp = nullptr, *pKp = nullptr, *pVp = nullptr, *pA = nullptr;
    cudaGetSymbolAddress(&pQp, g_Qp);
    cudaGetSymbolAddress(&pKp, g_Kp);
    cudaGetSymbolAddress(&pVp, g_Vp);
    cudaGetSymbolAddress(&pA, g_A);

    cudaFuncSetAttribute(zinv_kernel, cudaFuncAttributeMaxDynamicSharedMemorySize,
                         ZINV_SMEM_BYTES);
    cudaFuncSetAttribute(attn_kernel, cudaFuncAttributeMaxDynamicSharedMemorySize,
                         ATTN_SMEM_BYTES);

    dim3 gGemm(DD / 128, (BB * NN) / 128, 3);
    gemm512_kernel<<<gGemm, 256>>>(Q, K, V, Wq, bq, (float*)pQp, (float*)pKp,
                                   (float*)pVp);
    zinv_kernel<<<dim3(NN / 128, NN / 128, BB), 512, ZINV_SMEM_BYTES>>>();
    attn_kernel<<<dim3(NN / 128, HH, BB), 256, ATTN_SMEM_BYTES>>>();
    gemm512_kernel<<<dim3(DD / 128, (BB * NN) / 128, 1), 256>>>(
        (const float*)pA, nullptr, nullptr, Wo, bo, out, nullptr, nullptr);
}

// round 13
// speedup vs baseline: 6.3842x; 1.2325x over previous
#include <cuda_runtime.h>
#include <cuda_fp16.h>
#include <stdint.h>

#define BB 4
#define NN 2048
#define DD 512
#define HH 8
#define DKK 64

// fp16 scratch written by the projection kernel.
__device__ __align__(16) __half g_hQp[BB * NN * DD];   // [b][n][e]
__device__ __align__(16) __half g_hKp[BB * NN * DD];   // [b][n][e]
__device__ __align__(16) __half g_hVt[BB * DD * NN];   // [b][e][n]  (transposed)
__device__ float g_Zinv[(size_t)BB * NN * NN];
__device__ float g_A[BB * NN * DD];

__device__ __forceinline__ uint32_t f2h2(float lo, float hi) {
    uint32_t r;
    asm("cvt.rn.f16x2.f32 %0, %1, %2;" : "=r"(r) : "f"(hi), "f"(lo));
    return r;
}
__device__ __forceinline__ uint2 f4toh(float4 v) {
    return make_uint2(f2h2(v.x, v.y), f2h2(v.z, v.w));
}
__device__ __forceinline__ void mma16(float c[4], const uint32_t a[4],
                                      const uint32_t b[2]) {
    asm volatile(
        "mma.sync.aligned.m16n8k16.row.col.f32.f16.f16.f32 "
        "{%0,%1,%2,%3},{%4,%5,%6,%7},{%8,%9},{%0,%1,%2,%3};"
        : "+f"(c[0]), "+f"(c[1]), "+f"(c[2]), "+f"(c[3])
        : "r"(a[0]), "r"(a[1]), "r"(a[2]), "r"(a[3]), "r"(b[0]), "r"(b[1]));
}
__device__ __forceinline__ void ldsm4(uint32_t r[4], uint32_t a) {
    asm volatile(
        "ldmatrix.sync.aligned.m8n8.x4.shared.b16 {%0,%1,%2,%3}, [%4];"
        : "=r"(r[0]), "=r"(r[1]), "=r"(r[2]), "=r"(r[3])
        : "r"(a));
}
__device__ __forceinline__ uint32_t smem_u32(const void* p) {
    return (uint32_t)__cvta_generic_to_shared(p);
}
__device__ __forceinline__ void cpa16(uint32_t dst, const void* src) {
    asm volatile("cp.async.ca.shared.global [%0], [%1], 16;" ::"r"(dst),
                 "l"(src));
}
#define CP_COMMIT asm volatile("cp.async.commit_group;" ::: "memory")
#define CP_WAIT1 asm volatile("cp.async.wait_group 1;" ::: "memory")
#define CP_WAIT0 asm volatile("cp.async.wait_group 0;" ::: "memory")

#define LANE_RA(lane) ((((lane) >> 3) & 1) * 8 + ((lane)&7))
#define LANE_HA(lane) (((lane) >> 4) * 8)
#define LANE_RB(lane) ((((lane) >> 4)) * 8 + ((lane)&7))
#define LANE_HB(lane) ((((lane) >> 3) & 1) * 8)

// ---------------------------------------------------------------------------
// 512-K GEMM (fp16 mma): Y[row,e] = sum_d X[row,d]*W[e,d] + bias[e]
// Tile 128x128, BK=32, 256 thr, reg prefetch + ldmatrix (inputs fp32).
// mode 0 (proj): z=0 -> g_hQp (half), z=1 -> g_hKp (half),
//                z=2 -> g_hVt (half, TRANSPOSED per batch).
// mode 1 (final): fp32 out to Yf.
// ---------------------------------------------------------------------------
#define GSTR 20

__global__ __launch_bounds__(256, 2) void gemm512_kernel(
    const float* __restrict__ X0, const float* __restrict__ X1,
    const float* __restrict__ X2, const float* __restrict__ W,
    const float* __restrict__ bias, float* __restrict__ Yf, int mode) {
    const float* X = (blockIdx.z == 0) ? X0 : (blockIdx.z == 1) ? X1 : X2;

    __shared__ uint32_t sA[128][GSTR];
    __shared__ uint32_t sB[128][GSTR];

    const int tid = threadIdx.x;
    const int lane = tid & 31;
    const int warp = tid >> 5;
    const int wR = warp >> 2;
    const int wC = warp & 3;
    const int row0 = blockIdx.y * 128;
    const int e0 = blockIdx.x * 128;

    const int lr = tid >> 3;
    const int lcf = (tid & 7) * 4;
    const int lcu = (tid & 7) * 2;

    const uint32_t aB = smem_u32(&sA[0][0]);
    const uint32_t bB = smem_u32(&sB[0][0]);
    const int rA = LANE_RA(lane), hA = LANE_HA(lane);
    const int rB = LANE_RB(lane), hB = LANE_HB(lane);

    float acc[4][4][4] = {};
    float4 ra[4], rb[4];

    #pragma unroll
    for (int it = 0; it < 4; it++) {
        int r = lr + it * 32;
        ra[it] = *(const float4*)&X[(size_t)(row0 + r) * DD + lcf];
        rb[it] = *(const float4*)&W[(size_t)(e0 + r) * DD + lcf];
    }

    for (int k0 = 0; k0 < DD; k0 += 32) {
        #pragma unroll
        for (int it = 0; it < 4; it++) {
            int r = lr + it * 32;
            *(uint2*)&sA[r][lcu] = f4toh(ra[it]);
            *(uint2*)&sB[r][lcu] = f4toh(rb[it]);
        }
        __syncthreads();
        if (k0 + 32 < DD) {
            #pragma unroll
            for (int it = 0; it < 4; it++) {
                int r = lr + it * 32;
                ra[it] = *(const float4*)&X[(size_t)(row0 + r) * DD + k0 + 32 + lcf];
                rb[it] = *(const float4*)&W[(size_t)(e0 + r) * DD + k0 + 32 + lcf];
            }
        }
        #pragma unroll
        for (int kk = 0; kk < 32; kk += 16) {
            uint32_t af[4][4], bp[2][4];
            #pragma unroll
            for (int mt = 0; mt < 4; mt++)
                ldsm4(af[mt], aB + (wR * 64 + mt * 16 + rA) * (GSTR * 4) +
                                  (kk + hA) * 2);
            #pragma unroll
            for (int p = 0; p < 2; p++)
                ldsm4(bp[p], bB + (wC * 32 + p * 16 + rB) * (GSTR * 4) +
                                 (kk + hB) * 2);
            #pragma unroll
            for (int mt = 0; mt < 4; mt++)
                #pragma unroll
                for (int nt = 0; nt < 4; nt++)
                    mma16(acc[mt][nt], af[mt], &bp[nt >> 1][(nt & 1) * 2]);
        }
        __syncthreads();
    }

    #pragma unroll
    for (int mt = 0; mt < 4; mt++) {
        int r = row0 + wR * 64 + mt * 16 + (lane >> 2);
        #pragma unroll
        for (int nt = 0; nt < 4; nt++) {
            int c = e0 + wC * 32 + nt * 8 + (lane & 3) * 2;
            float b0 = bias[c], b1 = bias[c + 1];
            float v00 = acc[mt][nt][0] + b0, v01 = acc[mt][nt][1] + b1;
            float v10 = acc[mt][nt][2] + b0, v11 = acc[mt][nt][3] + b1;
            if (mode == 1) {
                *(float2*)&Yf[(size_t)r * DD + c] = make_float2(v00, v01);
                *(float2*)&Yf[(size_t)(r + 8) * DD + c] = make_float2(v10, v11);
            } else if (blockIdx.z < 2) {
                __half* Yh = blockIdx.z ? g_hKp : g_hQp;
                *(uint32_t*)&Yh[(size_t)r * DD + c] = f2h2(v00, v01);
                *(uint32_t*)&Yh[(size_t)(r + 8) * DD + c] = f2h2(v10, v11);
            } else {
                // V transposed: g_hVt[b][e][n]
                int bb = r >> 11, n = r & (NN - 1);
                size_t base = (size_t)bb * DD * NN;
                g_hVt[base + (size_t)c * NN + n] = __float2half_rn(v00);
                g_hVt[base + (size_t)(c + 1) * NN + n] = __float2half_rn(v01);
                g_hVt[base + (size_t)c * NN + n + 8] = __float2half_rn(v10);
                g_hVt[base + (size_t)(c + 1) * NN + n + 8] = __float2half_rn(v11);
            }
        }
    }
}

// ---------------------------------------------------------------------------
// Zinv[b,n,m] = 1 / sum_h exp( (q_h(n).k_h(m)) / 8 )
// Tile 128x128, 512 threads, 16 warps 32x32. BK=32 halves.
// fp16 inputs, cp.async 3-deep pipeline, ONE barrier per chunk.
// Buffer = sQ(128 rows) + sK(128 rows), stride GSTR u32 (80 B).
// ---------------------------------------------------------------------------
#define ZBUF (2 * 128 * GSTR)
#define ZINV_SMEM_BYTES (3 * ZBUF * 4)

__global__ __launch_bounds__(512) void zinv_kernel() {
    extern __shared__ uint32_t zsm[];

    const int tid = threadIdx.x;
    const int lane = tid & 31;
    const int warp = tid >> 5;
    const int wR = warp >> 2;
    const int wC = warp & 3;
    const int b = blockIdx.z;
    const int n0 = blockIdx.y * 128;
    const int m0 = blockIdx.x * 128;
    const __half* Qh = g_hQp + (size_t)b * NN * DD;
    const __half* Kh = g_hKp + (size_t)b * NN * DD;

    const uint32_t base0 = smem_u32(zsm);
    const int rA = LANE_RA(lane), hA = LANE_HA(lane);
    const int rB = LANE_RB(lane), hB = LANE_HB(lane);

    // cp mapping: row = tid>>2 (0..127), seg = tid&3 (16B each)
    const int crow = tid >> 2;
    const int cseg = tid & 3;

    float z[2][4][4] = {};
    float dot[2][4][4] = {};

    // Prologue: chunks 0,1 into bufs 0,1.
    #pragma unroll
    for (int pc = 0; pc < 2; pc++) {
        uint32_t bufB = base0 + pc * (ZBUF * 4);
        cpa16(bufB + (crow * GSTR + cseg * 4) * 4,
              Qh + (size_t)(n0 + crow) * DD + pc * 32 + cseg * 8);
        cpa16(bufB + ((128 + crow) * GSTR + cseg * 4) * 4,
              Kh + (size_t)(m0 + crow) * DD + pc * 32 + cseg * 8);
        CP_COMMIT;
    }

    for (int ch = 0; ch < 16; ch++) {
        if (ch == 15) { CP_WAIT0; } else { CP_WAIT1; }
        __syncthreads();

        const uint32_t qB = base0 + (ch % 3) * (ZBUF * 4);
        const uint32_t kB = qB + 128 * GSTR * 4;

        #pragma unroll
        for (int kk = 0; kk < 32; kk += 16) {
            uint32_t af[2][4], bp[2][4];
            #pragma unroll
            for (int mt = 0; mt < 2; mt++)
                ldsm4(af[mt], qB + (wR * 32 + mt * 16 + rA) * (GSTR * 4) +
                                  (kk + hA) * 2);
            #pragma unroll
            for (int p = 0; p < 2; p++)
                ldsm4(bp[p], kB + (wC * 32 + p * 16 + rB) * (GSTR * 4) +
                                 (kk + hB) * 2);
            #pragma unroll
            for (int mt = 0; mt < 2; mt++)
                #pragma unroll
                for (int nt = 0; nt < 4; nt++)
                    mma16(dot[mt][nt], af[mt], &bp[nt >> 1][(nt & 1) * 2]);
        }

        if (ch & 1) {  // head boundary: fold exp
            #pragma unroll
            for (int mt = 0; mt < 2; mt++)
                #pragma unroll
                for (int nt = 0; nt < 4; nt++)
                    #pragma unroll
                    for (int i = 0; i < 4; i++) {
                        z[mt][nt][i] += __expf(dot[mt][nt][i] * 0.125f);
                        dot[mt][nt][i] = 0.0f;
                    }
        }

        if (ch + 2 < 16) {  // stage chunk ch+2 (buf free since BAR above)
            uint32_t bufB = base0 + ((ch + 2) % 3) * (ZBUF * 4);
            int kb = (ch + 2) * 32;
            cpa16(bufB + (crow * GSTR + cseg * 4) * 4,
                  Qh + (size_t)(n0 + crow) * DD + kb + cseg * 8);
            cpa16(bufB + ((128 + crow) * GSTR + cseg * 4) * 4,
                  Kh + (size_t)(m0 + crow) * DD + kb + cseg * 8);
            CP_COMMIT;
        }
    }

    #pragma unroll
    for (int mt = 0; mt < 2; mt++) {
        int r = n0 + wR * 32 + mt * 16 + (lane >> 2);
        #pragma unroll
        for (int nt = 0; nt < 4; nt++) {
            int c = m0 + wC * 32 + nt * 8 + (lane & 3) * 2;
            *(float2*)&g_Zinv[((size_t)b * NN + r) * NN + c] =
                make_float2(1.0f / z[mt][nt][0], 1.0f / z[mt][nt][1]);
            *(float2*)&g_Zinv[((size_t)b * NN + r + 8) * NN + c] =
                make_float2(1.0f / z[mt][nt][2], 1.0f / z[mt][nt][3]);
        }
    }
}

// ---------------------------------------------------------------------------
// Attention with precomputed Zinv. Per block: (b,h,n-tile 128). 256 threads,
// 8 warps 4x2 (32x32 warp tiles). fp16 inputs; K and pre-transposed V staged
// via cp.async with 3 buffers; Q staged via cp.async in prologue.
// Smem rows (stride ASTR=36 u32): sQ[0,128) | sP[128,256) |
//   K bufs [256+buf*64) x3 | V bufs [448+buf*64) x3   => 640*36*4 = 92160 B.
// 2 barriers per 64-m chunk.
// ---------------------------------------------------------------------------
#define ASTR 36
#define ATTN_SMEM_BYTES (640 * ASTR * 4)

__global__ __launch_bounds__(256, 2) void attn_kernel() {
    extern __shared__ uint32_t asm_[];

    const int tid = threadIdx.x;
    const int lane = tid & 31;
    const int warp = tid >> 5;
    const int wR = warp >> 1;  // 0..3
    const int wC = warp & 1;   // 0..1
    const int b = blockIdx.z;
    const int h = blockIdx.y;
    const int n0 = blockIdx.x * 128;

    const __half* Qh = g_hQp + (size_t)b * NN * DD + h * DKK;
    const __half* Kh = g_hKp + (size_t)b * NN * DD + h * DKK;
    const __half* Vth = g_hVt + ((size_t)b * DD + h * DKK) * NN;
    const float* Zb = g_Zinv + (size_t)b * NN * NN;

    const uint32_t smB = smem_u32(asm_);
    const uint32_t qB = smB;
    const uint32_t pB = smB + 128 * ASTR * 4;
    const uint32_t kB0 = smB + 256 * ASTR * 4;
    const uint32_t vB0 = smB + 448 * ASTR * 4;
    const int rA = LANE_RA(lane), hA = LANE_HA(lane);
    const int rB = LANE_RB(lane), hB = LANE_HB(lane);

    // Q prologue: 128 rows x 8 segs of 16B; 4 per thread.
    {
        int qrow = tid >> 1;
        int sbase = (tid & 1) * 4;
        #pragma unroll
        for (int s = 0; s < 4; s++) {
            int seg = sbase + s;
            cpa16(qB + (qrow * ASTR + seg * 4) * 4,
                  Qh + (size_t)(n0 + qrow) * DD + seg * 8);
        }
        CP_COMMIT;
    }

    // K/V chunk cp mapping: row = tid>>2 (0..63), segs (tid&3) and (tid&3)+4.
    const int krow = tid >> 2;
    const int kseg = tid & 3;

    // Prologue: chunks 0,1.
    #pragma unroll
    for (int pc = 0; pc < 2; pc++) {
        uint32_t kBuf = kB0 + pc * (64 * ASTR * 4);
        uint32_t vBuf = vB0 + pc * (64 * ASTR * 4);
        #pragma unroll
        for (int s = 0; s < 2; s++) {
            int seg = kseg + s * 4;
            cpa16(kBuf + (krow * ASTR + seg * 4) * 4,
                  Kh + (size_t)(pc * 64 + krow) * DD + seg * 8);
            cpa16(vBuf + (krow * ASTR + seg * 4) * 4,
                  Vth + (size_t)krow * NN + pc * 64 + seg * 8);
        }
        CP_COMMIT;
    }

    const int erl = wR * 32 + (lane >> 2);
    const int ecl = wC * 32 + (lane & 3) * 2;

    float accO[2][4][4] = {};

    for (int c = 0; c < NN / 64; c++) {
        const int m0 = c * 64;

        // Zinv(c) register prefetch — hidden behind the S phase.
        float2 rz[2][4][2];
        #pragma unroll
        for (int mt = 0; mt < 2; mt++)
            #pragma unroll
            for (int nt = 0; nt < 4; nt++) {
                int rl = erl + mt * 16, cl = ecl + nt * 8;
                rz[mt][nt][0] =
                    *(const float2*)&Zb[(size_t)(n0 + rl) * NN + m0 + cl];
                rz[mt][nt][1] =
                    *(const float2*)&Zb[(size_t)(n0 + rl + 8) * NN + m0 + cl];
            }

        if (c == NN / 64 - 1) { CP_WAIT0; } else { CP_WAIT1; }
        __syncthreads();  // A: K/V(c) ready; PV(c-1) sP reads done

        const uint32_t kB = kB0 + (c % 3) * (64 * ASTR * 4);
        const uint32_t vB = vB0 + (c % 3) * (64 * ASTR * 4);

        // ---- S = Q.K^T (128x64, contract 64) ----
        float accS[2][4][4] = {};
        #pragma unroll
        for (int kk = 0; kk < 64; kk += 16) {
            uint32_t af[2][4], bp[2][4];
            #pragma unroll
            for (int mt = 0; mt < 2; mt++)
                ldsm4(af[mt], qB + (wR * 32 + mt * 16 + rA) * (ASTR * 4) +
                                  (kk + hA) * 2);
            #pragma unroll
            for (int p = 0; p < 2; p++)
                ldsm4(bp[p], kB + (wC * 32 + p * 16 + rB) * (ASTR * 4) +
                                 (kk + hB) * 2);
            #pragma unroll
            for (int mt = 0; mt < 2; mt++)
                #pragma unroll
                for (int nt = 0; nt < 4; nt++)
                    mma16(accS[mt][nt], af[mt], &bp[nt >> 1][(nt & 1) * 2]);
        }

        // P = exp(S/8) * Zinv -> sP (half2)
        uint32_t(*sP)[ASTR] = (uint32_t(*)[ASTR])(asm_ + 128 * ASTR);
        #pragma unroll
        for (int mt = 0; mt < 2; mt++) {
            int rl = erl + mt * 16;
            #pragma unroll
            for (int nt = 0; nt < 4; nt++) {
                int cu = wC * 16 + nt * 4 + (lane & 3);
                sP[rl][cu] =
                    f2h2(__expf(accS[mt][nt][0] * 0.125f) * rz[mt][nt][0].x,
                         __expf(accS[mt][nt][1] * 0.125f) * rz[mt][nt][0].y);
                sP[rl + 8][cu] =
                    f2h2(__expf(accS[mt][nt][2] * 0.125f) * rz[mt][nt][1].x,
                         __expf(accS[mt][nt][3] * 0.125f) * rz[mt][nt][1].y);
            }
        }
        __syncthreads();  // B: sP ready

        // ---- O += P.V (128x64, contract 64) ----
        #pragma unroll
        for (int kk = 0; kk < 64; kk += 16) {
            uint32_t af[2][4], bp[2][4];
            #pragma unroll
            for (int mt = 0; mt < 2; mt++)
                ldsm4(af[mt], pB + (wR * 32 + mt * 16 + rA) * (ASTR * 4) +
                                  (kk + hA) * 2);
            #pragma unroll
            for (int p = 0; p < 2; p++)
                ldsm4(bp[p], vB + (wC * 32 + p * 16 + rB) * (ASTR * 4) +
                                 (kk + hB) * 2);
            #pragma unroll
            for (int mt = 0; mt < 2; mt++)
                #pragma unroll
                for (int nt = 0; nt < 4; nt++)
                    mma16(accO[mt][nt], af[mt], &bp[nt >> 1][(nt & 1) * 2]);
        }

        // Stage chunk c+2 (its buffer's last reads were in iter c-1,
        // separated by BOTH barriers above).
        if (c + 2 < NN / 64) {
            uint32_t kBuf = kB0 + ((c + 2) % 3) * (64 * ASTR * 4);
            uint32_t vBuf = vB0 + ((c + 2) % 3) * (64 * ASTR * 4);
            int mb = m0 + 128;
            #pragma unroll
            for (int s = 0; s < 2; s++) {
                int seg = kseg + s * 4;
                cpa16(kBuf + (krow * ASTR + seg * 4) * 4,
                      Kh + (size_t)(mb + krow) * DD + seg * 8);
                cpa16(vBuf + (krow * ASTR + seg * 4) * 4,
                      Vth + (size_t)krow * NN + mb + seg * 8);
            }
            CP_COMMIT;
        }
    }

    #pragma unroll
    for (int mt = 0; mt < 2; mt++) {
        int r = n0 + wR * 32 + mt * 16 + (lane >> 2);
        #pragma unroll
        for (int nt = 0; nt < 4; nt++) {
            int cc = h * DKK + wC * 32 + nt * 8 + (lane & 3) * 2;
            *(float2*)&g_A[((size_t)b * NN + r) * DD + cc] =
                make_float2(accO[mt][nt][0], accO[mt][nt][1]);
            *(float2*)&g_A[((size_t)b * NN + r + 8) * DD + cc] =
                make_float2(accO[mt][nt][2], accO[mt][nt][3]);
        }
    }
}

extern "C" void kernel_launch(void* const* d_in, const int* in_sizes, int n_in,
                              void* d_out, int out_size) {
    const float* Q = (const float*)d_in[0];
    const float* K = (const float*)d_in[1];
    const float* V = (const float*)d_in[2];
    const float* Wq = (const float*)d_in[3];
    const float* bq = (const float*)d_in[4];
    const float* Wo = (const float*)d_in[5];
    const float* bo = (const float*)d_in[6];
    float* out = (float*)d_out;

    void* pA = nullptr;
    cudaGetSymbolAddress(&pA, g_A);

    cudaFuncSetAttribute(zinv_kernel, cudaFuncAttributeMaxDynamicSharedMemorySize,
                         ZINV_SMEM_BYTES);
    cudaFuncSetAttribute(attn_kernel, cudaFuncAttributeMaxDynamicSharedMemorySize,
                         ATTN_SMEM_BYTES);

    gemm512_kernel<<<dim3(DD / 128, (BB * NN) / 128, 3), 256>>>(
        Q, K, V, Wq, bq, nullptr, 0);
    zinv_kernel<<<dim3(NN / 128, NN / 128, BB), 512, ZINV_SMEM_BYTES>>>();
    attn_kernel<<<dim3(NN / 128, HH, BB), 256, ATTN_SMEM_BYTES>>>();
    gemm512_kernel<<<dim3(DD / 128, (BB * NN) / 128, 1), 256>>>(
        (const float*)pA, nullptr, nullptr, Wo, bo, out, 1);
}